// round 3
// baseline (speedup 1.0000x reference)
#include <cuda_runtime.h>
#include <math.h>
#include <stdint.h>

#define DIM 768
#define MLPD 3072
#define HEADS 12
#define DH 64
#define TOK 4096          // 4 * 1024
#define SEQ 1024
#define NB 4

// ---------------- scratch buffers (device globals; no allocation allowed) ----
__device__ float g_h[TOK * DIM];       // LN output
__device__ float g_qkv[TOK * 3 * DIM]; // qkv projections
__device__ float g_attn[TOK * DIM];    // attention output (pre o-proj)
__device__ float g_mlp[TOK * MLPD];    // MLP hidden

// ---------------- helpers ------------------------------------------------------
__device__ __forceinline__ uint32_t f2tf32(float f) {
    uint32_t u;
    asm("cvt.rna.tf32.f32 %0, %1;" : "=r"(u) : "f"(f));
    return u;
}

// ---------------- LayerNorm: one block per row --------------------------------
__global__ void layernorm_kernel(const float* __restrict__ x,
                                 const float* __restrict__ w,
                                 const float* __restrict__ b,
                                 float* __restrict__ out) {
    int row = blockIdx.x;
    const float* xr = x + (size_t)row * DIM;
    float vals[3];
    float s = 0.f, ss = 0.f;
#pragma unroll
    for (int i = 0; i < 3; ++i) {
        float v = xr[threadIdx.x + 256 * i];
        vals[i] = v;
        s += v;
        ss += v * v;
    }
#pragma unroll
    for (int o = 16; o; o >>= 1) {
        s  += __shfl_xor_sync(0xffffffffu, s, o);
        ss += __shfl_xor_sync(0xffffffffu, ss, o);
    }
    __shared__ float shs[8], shss[8];
    __shared__ float mean_s, rstd_s;
    int wid = threadIdx.x >> 5, lid = threadIdx.x & 31;
    if (lid == 0) { shs[wid] = s; shss[wid] = ss; }
    __syncthreads();
    if (threadIdx.x == 0) {
        float S = 0.f, SS = 0.f;
#pragma unroll
        for (int i = 0; i < 8; ++i) { S += shs[i]; SS += shss[i]; }
        float mean = S * (1.0f / DIM);
        float var  = SS * (1.0f / DIM) - mean * mean;
        mean_s = mean;
        rstd_s = rsqrtf(var + 1e-5f);
    }
    __syncthreads();
    float mean = mean_s, rstd = rstd_s;
    float* orow = out + (size_t)row * DIM;
#pragma unroll
    for (int i = 0; i < 3; ++i) {
        int idx = threadIdx.x + 256 * i;
        orow[idx] = (vals[i] - mean) * rstd * w[idx] + b[idx];
    }
}

// ---------------- TF32 tensor-core GEMM ---------------------------------------
// C[M,N] = op( A[M,K] @ B[K,N] + bias ) (+ residual read from C itself)
// block tile 128x128, K-tile 32, 8 warps (4x2), warp tile 32x64,
// per warp 2x8 m16n8k8 tf32 MMAs per k8-step.
// Requires M%128==0, N%128==0, K%32==0 (true at all call sites).
template <bool HAS_BIAS, bool RESID, bool DO_GELU>
__global__ __launch_bounds__(256, 2) void tf32_gemm_kernel(
    const float* __restrict__ A, const float* __restrict__ B,
    const float* __restrict__ bias, float* __restrict__ C,
    int M, int N, int K) {
    // A row-major [m][k], stride 36 words: fragment-load bank = (4m+k)%32,
    // distinct over (group 0..7, tig 0..3) -> conflict free.
    __shared__ uint32_t As[128][36];
    // B row-major [k][n], stride 136 words: bank = (8k+n)%32, distinct -> conflict free.
    __shared__ uint32_t Bs[32][136];

    const int tid   = threadIdx.x;
    const int lane  = tid & 31;
    const int wid   = tid >> 5;
    const int group = lane >> 2;   // 0..7
    const int tig   = lane & 3;    // 0..3
    const int wm0   = (wid >> 1) * 32;  // warp row offset 0..96
    const int wn0   = (wid & 1) * 64;   // warp col offset 0/64

    const float* Ab = A + (size_t)(blockIdx.y * 128) * K;
    const float* Bb = B + (size_t)(blockIdx.x * 128);

    float acc[2][8][4];
#pragma unroll
    for (int mi = 0; mi < 2; ++mi)
#pragma unroll
        for (int ni = 0; ni < 8; ++ni)
#pragma unroll
            for (int r = 0; r < 4; ++r) acc[mi][ni][r] = 0.f;

    for (int kt = 0; kt < K; kt += 32) {
        __syncthreads();
#pragma unroll
        for (int i = 0; i < 4; ++i) {
            int fi = tid + i * 256;          // float4 index 0..1023
            // A tile: 128 rows x 32 cols (8 float4/row)
            int ar  = fi >> 3;
            int ac4 = fi & 7;
            float4 va = *(const float4*)&Ab[(size_t)ar * K + kt + ac4 * 4];
            uint4 ua = make_uint4(f2tf32(va.x), f2tf32(va.y),
                                  f2tf32(va.z), f2tf32(va.w));
            *(uint4*)&As[ar][ac4 * 4] = ua;
            // B tile: 32 rows x 128 cols (32 float4/row)
            int br  = fi >> 5;
            int bc4 = fi & 31;
            float4 vb = *(const float4*)&Bb[(size_t)(kt + br) * N + bc4 * 4];
            uint4 ub = make_uint4(f2tf32(vb.x), f2tf32(vb.y),
                                  f2tf32(vb.z), f2tf32(vb.w));
            *(uint4*)&Bs[br][bc4 * 4] = ub;
        }
        __syncthreads();

#pragma unroll
        for (int kk = 0; kk < 32; kk += 8) {
            uint32_t af[2][4];
#pragma unroll
            for (int mi = 0; mi < 2; ++mi) {
                int mrow = wm0 + mi * 16 + group;
                af[mi][0] = As[mrow][kk + tig];
                af[mi][1] = As[mrow + 8][kk + tig];
                af[mi][2] = As[mrow][kk + tig + 4];
                af[mi][3] = As[mrow + 8][kk + tig + 4];
            }
#pragma unroll
            for (int ni = 0; ni < 8; ++ni) {
                uint32_t b0 = Bs[kk + tig][wn0 + ni * 8 + group];
                uint32_t b1 = Bs[kk + tig + 4][wn0 + ni * 8 + group];
#pragma unroll
                for (int mi = 0; mi < 2; ++mi) {
                    asm volatile(
                        "mma.sync.aligned.m16n8k8.row.col.f32.tf32.tf32.f32 "
                        "{%0,%1,%2,%3}, {%4,%5,%6,%7}, {%8,%9}, {%0,%1,%2,%3};"
                        : "+f"(acc[mi][ni][0]), "+f"(acc[mi][ni][1]),
                          "+f"(acc[mi][ni][2]), "+f"(acc[mi][ni][3])
                        : "r"(af[mi][0]), "r"(af[mi][1]),
                          "r"(af[mi][2]), "r"(af[mi][3]),
                          "r"(b0), "r"(b1));
                }
            }
        }
    }

    // epilogue
    const int base_m = blockIdx.y * 128 + wm0;
    const int base_n = blockIdx.x * 128 + wn0;
#pragma unroll
    for (int mi = 0; mi < 2; ++mi) {
#pragma unroll
        for (int rr = 0; rr < 2; ++rr) {
            int row = base_m + mi * 16 + rr * 8 + group;
#pragma unroll
            for (int ni = 0; ni < 8; ++ni) {
                int col = base_n + ni * 8 + tig * 2;
                float v0 = acc[mi][ni][rr * 2 + 0];
                float v1 = acc[mi][ni][rr * 2 + 1];
                if (HAS_BIAS) { v0 += bias[col]; v1 += bias[col + 1]; }
                if (DO_GELU) {
                    v0 = 0.5f * v0 * (1.0f + erff(v0 * 0.70710678118654752f));
                    v1 = 0.5f * v1 * (1.0f + erff(v1 * 0.70710678118654752f));
                }
                float* p = C + (size_t)row * N + col;
                if (RESID) {
                    float2 r = *(float2*)p;
                    v0 += r.x; v1 += r.y;
                }
                *(float2*)p = make_float2(v0, v1);
            }
        }
    }
}

// ---------------- Fused flash attention (fp32) -------------------------------
// grid: (SEQ/128, NB*HEADS), block: 128 threads, each thread owns one query row
__global__ __launch_bounds__(128) void attention_kernel(
    const float* __restrict__ qkv, float* __restrict__ out) {
    const int bh = blockIdx.y;
    const int b = bh / HEADS;
    const int h = bh % HEADS;
    const int qrow = blockIdx.x * 128 + threadIdx.x;

    const float* qb = qkv + ((size_t)(b * SEQ + qrow)) * (3 * DIM) + h * DH;
    float q[DH];
#pragma unroll
    for (int d = 0; d < DH; ++d) q[d] = qb[d] * 0.125f;  // 1/sqrt(64)

    __shared__ float Ks[64][64];
    __shared__ float Vs[64][64];

    float m = -1e30f, l = 0.f;
    float acc[DH];
#pragma unroll
    for (int d = 0; d < DH; ++d) acc[d] = 0.f;

    for (int jt = 0; jt < SEQ / 64; ++jt) {
        __syncthreads();
        const float* kb = qkv + ((size_t)(b * SEQ + jt * 64)) * (3 * DIM) + DIM + h * DH;
        const float* vb = kb + DIM;
#pragma unroll
        for (int f = 0; f < 8; ++f) {  // 1024 float4 / 128 threads = 8 each
            int idx = threadIdx.x * 8 + f;
            int r = idx >> 4;
            int c = (idx & 15) << 2;
            *(float4*)&Ks[r][c] = *(const float4*)&kb[(size_t)r * (3 * DIM) + c];
            *(float4*)&Vs[r][c] = *(const float4*)&vb[(size_t)r * (3 * DIM) + c];
        }
        __syncthreads();

#pragma unroll 1
        for (int jc = 0; jc < 64; jc += 16) {
            float s[16];
            float tmax = m;
#pragma unroll
            for (int j = 0; j < 16; ++j) {
                float sv = 0.f;
#pragma unroll
                for (int d = 0; d < DH; ++d) sv += q[d] * Ks[jc + j][d];
                s[j] = sv;
                tmax = fmaxf(tmax, sv);
            }
            float corr = __expf(m - tmax);
            m = tmax;
            l *= corr;
#pragma unroll
            for (int d = 0; d < DH; ++d) acc[d] *= corr;
#pragma unroll
            for (int j = 0; j < 16; ++j) {
                float p = __expf(s[j] - m);
                l += p;
#pragma unroll
                for (int d = 0; d < DH; ++d) acc[d] += p * Vs[jc + j][d];
            }
        }
    }
    float inv = 1.0f / l;
    float* ob = out + ((size_t)(b * SEQ + qrow)) * DIM + h * DH;
#pragma unroll
    for (int d = 0; d < DH; ++d) ob[d] = acc[d] * inv;
}

// ---------------- host side ---------------------------------------------------
extern "C" void kernel_launch(void* const* d_in, const int* in_sizes, int n_in,
                              void* d_out, int out_size) {
    const float* x      = (const float*)d_in[0];
    const float* ln1_w  = (const float*)d_in[1];
    const float* ln1_b  = (const float*)d_in[2];
    const float* w_qkv  = (const float*)d_in[3];
    const float* w_o    = (const float*)d_in[4];
    const float* b_o    = (const float*)d_in[5];
    const float* ln2_w  = (const float*)d_in[6];
    const float* ln2_b  = (const float*)d_in[7];
    const float* w1     = (const float*)d_in[8];
    const float* b1     = (const float*)d_in[9];
    const float* w2     = (const float*)d_in[10];
    const float* b2     = (const float*)d_in[11];

    float* X = (float*)d_out;

    float *pH, *pQKV, *pATT, *pMLP;
    cudaGetSymbolAddress((void**)&pH,   g_h);
    cudaGetSymbolAddress((void**)&pQKV, g_qkv);
    cudaGetSymbolAddress((void**)&pATT, g_attn);
    cudaGetSymbolAddress((void**)&pMLP, g_mlp);

    cudaMemcpyAsync(X, x, (size_t)TOK * DIM * sizeof(float),
                    cudaMemcpyDeviceToDevice);

    for (int l = 0; l < 6; ++l) {
        const float* l1w = ln1_w + l * DIM;
        const float* l1b = ln1_b + l * DIM;
        const float* wqkv = w_qkv + (size_t)l * DIM * 3 * DIM;
        const float* wo   = w_o   + (size_t)l * DIM * DIM;
        const float* bo   = b_o   + l * DIM;
        const float* l2w = ln2_w + l * DIM;
        const float* l2b = ln2_b + l * DIM;
        const float* W1 = w1 + (size_t)l * DIM * MLPD;
        const float* B1 = b1 + l * MLPD;
        const float* W2 = w2 + (size_t)l * MLPD * DIM;
        const float* B2 = b2 + l * DIM;

        // LN1
        layernorm_kernel<<<TOK, 256>>>(X, l1w, l1b, pH);
        // QKV: [4096,768] @ [768,2304]  (no bias)
        tf32_gemm_kernel<false, false, false>
            <<<dim3(3 * DIM / 128, TOK / 128), 256>>>(pH, wqkv, nullptr, pQKV,
                                                      TOK, 3 * DIM, DIM);
        // fused attention
        attention_kernel<<<dim3(SEQ / 128, NB * HEADS), 128>>>(pQKV, pATT);
        // O-proj + bias + residual into X
        tf32_gemm_kernel<true, true, false>
            <<<dim3(DIM / 128, TOK / 128), 256>>>(pATT, wo, bo, X,
                                                  TOK, DIM, DIM);
        // LN2
        layernorm_kernel<<<TOK, 256>>>(X, l2w, l2b, pH);
        // MLP1 + bias + exact GELU
        tf32_gemm_kernel<true, false, true>
            <<<dim3(MLPD / 128, TOK / 128), 256>>>(pH, W1, B1, pMLP,
                                                   TOK, MLPD, DIM);
        // MLP2 + bias + residual into X
        tf32_gemm_kernel<true, true, false>
            <<<dim3(DIM / 128, TOK / 128), 256>>>(pMLP, W2, B2, X,
                                                  TOK, DIM, MLPD);
    }
}

// round 4
// speedup vs baseline: 1.0040x; 1.0040x over previous
#include <cuda_runtime.h>
#include <math.h>
#include <stdint.h>

#define DIM 768
#define MLPD 3072
#define HEADS 12
#define DH 64
#define TOK 4096          // 4 * 1024
#define SEQ 1024
#define NB 4

// ---------------- scratch buffers (device globals; no allocation allowed) ----
__device__ float g_h[TOK * DIM];       // LN output
__device__ float g_qkv[TOK * 3 * DIM]; // qkv projections
__device__ float g_attn[TOK * DIM];    // attention output (pre o-proj)
__device__ float g_mlp[TOK * MLPD];    // MLP hidden

// ---------------- helpers ------------------------------------------------------
__device__ __forceinline__ uint32_t f2tf32(float f) {
    uint32_t u;
    asm("cvt.rna.tf32.f32 %0, %1;" : "=r"(u) : "f"(f));
    return u;
}

// ---------------- LayerNorm: one block per row --------------------------------
__global__ void layernorm_kernel(const float* __restrict__ x,
                                 const float* __restrict__ w,
                                 const float* __restrict__ b,
                                 float* __restrict__ out) {
    int row = blockIdx.x;
    const float* xr = x + (size_t)row * DIM;
    float vals[3];
    float s = 0.f, ss = 0.f;
#pragma unroll
    for (int i = 0; i < 3; ++i) {
        float v = xr[threadIdx.x + 256 * i];
        vals[i] = v;
        s += v;
        ss += v * v;
    }
#pragma unroll
    for (int o = 16; o; o >>= 1) {
        s  += __shfl_xor_sync(0xffffffffu, s, o);
        ss += __shfl_xor_sync(0xffffffffu, ss, o);
    }
    __shared__ float shs[8], shss[8];
    __shared__ float mean_s, rstd_s;
    int wid = threadIdx.x >> 5, lid = threadIdx.x & 31;
    if (lid == 0) { shs[wid] = s; shss[wid] = ss; }
    __syncthreads();
    if (threadIdx.x == 0) {
        float S = 0.f, SS = 0.f;
#pragma unroll
        for (int i = 0; i < 8; ++i) { S += shs[i]; SS += shss[i]; }
        float mean = S * (1.0f / DIM);
        float var  = SS * (1.0f / DIM) - mean * mean;
        mean_s = mean;
        rstd_s = rsqrtf(var + 1e-5f);
    }
    __syncthreads();
    float mean = mean_s, rstd = rstd_s;
    float* orow = out + (size_t)row * DIM;
#pragma unroll
    for (int i = 0; i < 3; ++i) {
        int idx = threadIdx.x + 256 * i;
        orow[idx] = (vals[i] - mean) * rstd * w[idx] + b[idx];
    }
}

// ---------------- TF32 tensor-core GEMM ---------------------------------------
// C[M,N] = op( A[M,K] @ B[K,N] + bias ) (+ residual read from C itself)
// block tile 128x128, K-tile 32, 8 warps (4x2), warp tile 32x64,
// per warp 2x8 m16n8k8 tf32 MMAs per k8-step.
// Requires M%128==0, N%128==0, K%32==0 (true at all call sites).
template <bool HAS_BIAS, bool RESID, bool DO_GELU>
__global__ __launch_bounds__(256, 2) void tf32_gemm_kernel(
    const float* __restrict__ A, const float* __restrict__ B,
    const float* __restrict__ bias, float* __restrict__ C,
    int M, int N, int K) {
    // A row-major [m][k], stride 36 words: fragment-load bank = (4m+k)%32,
    // distinct over (group 0..7, tig 0..3) -> conflict free.
    __shared__ uint32_t As[128][36];
    // B row-major [k][n], stride 136 words: bank = (8k+n)%32, distinct -> conflict free.
    __shared__ uint32_t Bs[32][136];

    const int tid   = threadIdx.x;
    const int lane  = tid & 31;
    const int wid   = tid >> 5;
    const int group = lane >> 2;   // 0..7
    const int tig   = lane & 3;    // 0..3
    const int wm0   = (wid >> 1) * 32;  // warp row offset 0..96
    const int wn0   = (wid & 1) * 64;   // warp col offset 0/64

    const float* Ab = A + (size_t)(blockIdx.y * 128) * K;
    const float* Bb = B + (size_t)(blockIdx.x * 128);

    float acc[2][8][4];
#pragma unroll
    for (int mi = 0; mi < 2; ++mi)
#pragma unroll
        for (int ni = 0; ni < 8; ++ni)
#pragma unroll
            for (int r = 0; r < 4; ++r) acc[mi][ni][r] = 0.f;

    for (int kt = 0; kt < K; kt += 32) {
        __syncthreads();
#pragma unroll
        for (int i = 0; i < 4; ++i) {
            int fi = tid + i * 256;          // float4 index 0..1023
            // A tile: 128 rows x 32 cols (8 float4/row)
            int ar  = fi >> 3;
            int ac4 = fi & 7;
            float4 va = *(const float4*)&Ab[(size_t)ar * K + kt + ac4 * 4];
            uint4 ua = make_uint4(f2tf32(va.x), f2tf32(va.y),
                                  f2tf32(va.z), f2tf32(va.w));
            *(uint4*)&As[ar][ac4 * 4] = ua;
            // B tile: 32 rows x 128 cols (32 float4/row)
            int br  = fi >> 5;
            int bc4 = fi & 31;
            float4 vb = *(const float4*)&Bb[(size_t)(kt + br) * N + bc4 * 4];
            uint4 ub = make_uint4(f2tf32(vb.x), f2tf32(vb.y),
                                  f2tf32(vb.z), f2tf32(vb.w));
            *(uint4*)&Bs[br][bc4 * 4] = ub;
        }
        __syncthreads();

#pragma unroll
        for (int kk = 0; kk < 32; kk += 8) {
            uint32_t af[2][4];
#pragma unroll
            for (int mi = 0; mi < 2; ++mi) {
                int mrow = wm0 + mi * 16 + group;
                af[mi][0] = As[mrow][kk + tig];
                af[mi][1] = As[mrow + 8][kk + tig];
                af[mi][2] = As[mrow][kk + tig + 4];
                af[mi][3] = As[mrow + 8][kk + tig + 4];
            }
#pragma unroll
            for (int ni = 0; ni < 8; ++ni) {
                uint32_t b0 = Bs[kk + tig][wn0 + ni * 8 + group];
                uint32_t b1 = Bs[kk + tig + 4][wn0 + ni * 8 + group];
#pragma unroll
                for (int mi = 0; mi < 2; ++mi) {
                    asm volatile(
                        "mma.sync.aligned.m16n8k8.row.col.f32.tf32.tf32.f32 "
                        "{%0,%1,%2,%3}, {%4,%5,%6,%7}, {%8,%9}, {%0,%1,%2,%3};"
                        : "+f"(acc[mi][ni][0]), "+f"(acc[mi][ni][1]),
                          "+f"(acc[mi][ni][2]), "+f"(acc[mi][ni][3])
                        : "r"(af[mi][0]), "r"(af[mi][1]),
                          "r"(af[mi][2]), "r"(af[mi][3]),
                          "r"(b0), "r"(b1));
                }
            }
        }
    }

    // epilogue
    const int base_m = blockIdx.y * 128 + wm0;
    const int base_n = blockIdx.x * 128 + wn0;
#pragma unroll
    for (int mi = 0; mi < 2; ++mi) {
#pragma unroll
        for (int rr = 0; rr < 2; ++rr) {
            int row = base_m + mi * 16 + rr * 8 + group;
#pragma unroll
            for (int ni = 0; ni < 8; ++ni) {
                int col = base_n + ni * 8 + tig * 2;
                float v0 = acc[mi][ni][rr * 2 + 0];
                float v1 = acc[mi][ni][rr * 2 + 1];
                if (HAS_BIAS) { v0 += bias[col]; v1 += bias[col + 1]; }
                if (DO_GELU) {
                    v0 = 0.5f * v0 * (1.0f + erff(v0 * 0.70710678118654752f));
                    v1 = 0.5f * v1 * (1.0f + erff(v1 * 0.70710678118654752f));
                }
                float* p = C + (size_t)row * N + col;
                if (RESID) {
                    float2 r = *(float2*)p;
                    v0 += r.x; v1 += r.y;
                }
                *(float2*)p = make_float2(v0, v1);
            }
        }
    }
}

// ---------------- Fused flash attention (fp32) -------------------------------
// grid: (SEQ/128, NB*HEADS), block: 128 threads, each thread owns one query row
__global__ __launch_bounds__(128) void attention_kernel(
    const float* __restrict__ qkv, float* __restrict__ out) {
    const int bh = blockIdx.y;
    const int b = bh / HEADS;
    const int h = bh % HEADS;
    const int qrow = blockIdx.x * 128 + threadIdx.x;

    const float* qb = qkv + ((size_t)(b * SEQ + qrow)) * (3 * DIM) + h * DH;
    float q[DH];
#pragma unroll
    for (int d = 0; d < DH; ++d) q[d] = qb[d] * 0.125f;  // 1/sqrt(64)

    __shared__ float Ks[64][64];
    __shared__ float Vs[64][64];

    float m = -1e30f, l = 0.f;
    float acc[DH];
#pragma unroll
    for (int d = 0; d < DH; ++d) acc[d] = 0.f;

    for (int jt = 0; jt < SEQ / 64; ++jt) {
        __syncthreads();
        const float* kb = qkv + ((size_t)(b * SEQ + jt * 64)) * (3 * DIM) + DIM + h * DH;
        const float* vb = kb + DIM;
#pragma unroll
        for (int f = 0; f < 8; ++f) {  // 1024 float4 / 128 threads = 8 each
            int idx = threadIdx.x * 8 + f;
            int r = idx >> 4;
            int c = (idx & 15) << 2;
            *(float4*)&Ks[r][c] = *(const float4*)&kb[(size_t)r * (3 * DIM) + c];
            *(float4*)&Vs[r][c] = *(const float4*)&vb[(size_t)r * (3 * DIM) + c];
        }
        __syncthreads();

#pragma unroll 1
        for (int jc = 0; jc < 64; jc += 16) {
            float s[16];
            float tmax = m;
#pragma unroll
            for (int j = 0; j < 16; ++j) {
                float sv = 0.f;
#pragma unroll
                for (int d = 0; d < DH; ++d) sv += q[d] * Ks[jc + j][d];
                s[j] = sv;
                tmax = fmaxf(tmax, sv);
            }
            float corr = __expf(m - tmax);
            m = tmax;
            l *= corr;
#pragma unroll
            for (int d = 0; d < DH; ++d) acc[d] *= corr;
#pragma unroll
            for (int j = 0; j < 16; ++j) {
                float p = __expf(s[j] - m);
                l += p;
#pragma unroll
                for (int d = 0; d < DH; ++d) acc[d] += p * Vs[jc + j][d];
            }
        }
    }
    float inv = 1.0f / l;
    float* ob = out + ((size_t)(b * SEQ + qrow)) * DIM + h * DH;
#pragma unroll
    for (int d = 0; d < DH; ++d) ob[d] = acc[d] * inv;
}

// ---------------- host side ---------------------------------------------------
extern "C" void kernel_launch(void* const* d_in, const int* in_sizes, int n_in,
                              void* d_out, int out_size) {
    const float* x      = (const float*)d_in[0];
    const float* ln1_w  = (const float*)d_in[1];
    const float* ln1_b  = (const float*)d_in[2];
    const float* w_qkv  = (const float*)d_in[3];
    const float* w_o    = (const float*)d_in[4];
    const float* b_o    = (const float*)d_in[5];
    const float* ln2_w  = (const float*)d_in[6];
    const float* ln2_b  = (const float*)d_in[7];
    const float* w1     = (const float*)d_in[8];
    const float* b1     = (const float*)d_in[9];
    const float* w2     = (const float*)d_in[10];
    const float* b2     = (const float*)d_in[11];

    float* X = (float*)d_out;

    float *pH, *pQKV, *pATT, *pMLP;
    cudaGetSymbolAddress((void**)&pH,   g_h);
    cudaGetSymbolAddress((void**)&pQKV, g_qkv);
    cudaGetSymbolAddress((void**)&pATT, g_attn);
    cudaGetSymbolAddress((void**)&pMLP, g_mlp);

    cudaMemcpyAsync(X, x, (size_t)TOK * DIM * sizeof(float),
                    cudaMemcpyDeviceToDevice);

    for (int l = 0; l < 6; ++l) {
        const float* l1w = ln1_w + l * DIM;
        const float* l1b = ln1_b + l * DIM;
        const float* wqkv = w_qkv + (size_t)l * DIM * 3 * DIM;
        const float* wo   = w_o   + (size_t)l * DIM * DIM;
        const float* bo   = b_o   + l * DIM;
        const float* l2w = ln2_w + l * DIM;
        const float* l2b = ln2_b + l * DIM;
        const float* W1 = w1 + (size_t)l * DIM * MLPD;
        const float* B1 = b1 + l * MLPD;
        const float* W2 = w2 + (size_t)l * MLPD * DIM;
        const float* B2 = b2 + l * DIM;

        // LN1
        layernorm_kernel<<<TOK, 256>>>(X, l1w, l1b, pH);
        // QKV: [4096,768] @ [768,2304]  (no bias)
        tf32_gemm_kernel<false, false, false>
            <<<dim3(3 * DIM / 128, TOK / 128), 256>>>(pH, wqkv, nullptr, pQKV,
                                                      TOK, 3 * DIM, DIM);
        // fused attention
        attention_kernel<<<dim3(SEQ / 128, NB * HEADS), 128>>>(pQKV, pATT);
        // O-proj + bias + residual into X
        tf32_gemm_kernel<true, true, false>
            <<<dim3(DIM / 128, TOK / 128), 256>>>(pATT, wo, bo, X,
                                                  TOK, DIM, DIM);
        // LN2
        layernorm_kernel<<<TOK, 256>>>(X, l2w, l2b, pH);
        // MLP1 + bias + exact GELU
        tf32_gemm_kernel<true, false, true>
            <<<dim3(MLPD / 128, TOK / 128), 256>>>(pH, W1, B1, pMLP,
                                                   TOK, MLPD, DIM);
        // MLP2 + bias + residual into X
        tf32_gemm_kernel<true, true, false>
            <<<dim3(DIM / 128, TOK / 128), 256>>>(pMLP, W2, B2, X,
                                                  TOK, DIM, MLPD);
    }
}

// round 5
// speedup vs baseline: 1.9225x; 1.9149x over previous
#include <cuda_runtime.h>
#include <math.h>
#include <stdint.h>

#define DIM 768
#define MLPD 3072
#define HEADS 12
#define DH 64
#define TOK 4096          // 4 * 1024
#define SEQ 1024
#define NB 4

// ---------------- scratch buffers (device globals; no allocation allowed) ----
__device__ float g_h[TOK * DIM];       // LN output
__device__ float g_qkv[TOK * 3 * DIM]; // qkv projections
__device__ float g_attn[TOK * DIM];    // attention output (pre o-proj)
__device__ float g_mlp[TOK * MLPD];    // MLP hidden

// ---------------- helpers ------------------------------------------------------
__device__ __forceinline__ uint32_t f2tf32(float f) {
    uint32_t u;
    asm("cvt.rna.tf32.f32 %0, %1;" : "=r"(u) : "f"(f));
    return u;
}

__device__ __forceinline__ void mma_tf32(float c[4], const uint32_t a[4],
                                         uint32_t b0, uint32_t b1) {
    asm volatile(
        "mma.sync.aligned.m16n8k8.row.col.f32.tf32.tf32.f32 "
        "{%0,%1,%2,%3}, {%4,%5,%6,%7}, {%8,%9}, {%0,%1,%2,%3};"
        : "+f"(c[0]), "+f"(c[1]), "+f"(c[2]), "+f"(c[3])
        : "r"(a[0]), "r"(a[1]), "r"(a[2]), "r"(a[3]), "r"(b0), "r"(b1));
}

// ---------------- LayerNorm: one block per row --------------------------------
__global__ void layernorm_kernel(const float* __restrict__ x,
                                 const float* __restrict__ w,
                                 const float* __restrict__ b,
                                 float* __restrict__ out) {
    int row = blockIdx.x;
    const float* xr = x + (size_t)row * DIM;
    float vals[3];
    float s = 0.f, ss = 0.f;
#pragma unroll
    for (int i = 0; i < 3; ++i) {
        float v = xr[threadIdx.x + 256 * i];
        vals[i] = v;
        s += v;
        ss += v * v;
    }
#pragma unroll
    for (int o = 16; o; o >>= 1) {
        s  += __shfl_xor_sync(0xffffffffu, s, o);
        ss += __shfl_xor_sync(0xffffffffu, ss, o);
    }
    __shared__ float shs[8], shss[8];
    __shared__ float mean_s, rstd_s;
    int wid = threadIdx.x >> 5, lid = threadIdx.x & 31;
    if (lid == 0) { shs[wid] = s; shss[wid] = ss; }
    __syncthreads();
    if (threadIdx.x == 0) {
        float S = 0.f, SS = 0.f;
#pragma unroll
        for (int i = 0; i < 8; ++i) { S += shs[i]; SS += shss[i]; }
        float mean = S * (1.0f / DIM);
        float var  = SS * (1.0f / DIM) - mean * mean;
        mean_s = mean;
        rstd_s = rsqrtf(var + 1e-5f);
    }
    __syncthreads();
    float mean = mean_s, rstd = rstd_s;
    float* orow = out + (size_t)row * DIM;
#pragma unroll
    for (int i = 0; i < 3; ++i) {
        int idx = threadIdx.x + 256 * i;
        orow[idx] = (vals[i] - mean) * rstd * w[idx] + b[idx];
    }
}

// ---------------- TF32 tensor-core GEMM, double-buffered ----------------------
// C[M,N] = op( A[M,K] @ B[K,N] + bias ) (+ residual)
// block tile 128x128, K-tile 32, 8 warps (4x2), warp tile 32x64.
// Dynamic smem: As[2][128][36] + Bs[2][32][136] (uint32 tf32).
#define GEMM_SMEM_WORDS (2 * 128 * 36 + 2 * 32 * 136)
#define GEMM_SMEM_BYTES (GEMM_SMEM_WORDS * 4)

template <bool HAS_BIAS, bool RESID, bool DO_GELU>
__global__ __launch_bounds__(256, 2) void tf32_gemm_kernel(
    const float* __restrict__ A, const float* __restrict__ B,
    const float* __restrict__ bias, float* __restrict__ C,
    int M, int N, int K) {
    extern __shared__ uint32_t smem[];
    typedef uint32_t ATile[128][36];
    typedef uint32_t BTile[32][136];
    ATile* As = (ATile*)smem;
    BTile* Bs = (BTile*)(smem + 2 * 128 * 36);

    const int tid   = threadIdx.x;
    const int lane  = tid & 31;
    const int wid   = tid >> 5;
    const int group = lane >> 2;   // 0..7
    const int tig   = lane & 3;    // 0..3
    const int wm0   = (wid >> 1) * 32;  // warp row offset 0..96
    const int wn0   = (wid & 1) * 64;   // warp col offset 0/64

    const float* Ab = A + (size_t)(blockIdx.y * 128) * K;
    const float* Bb = B + (size_t)(blockIdx.x * 128);

    // per-thread load coordinates (fixed across tiles)
    const int ar  = (tid >> 3) + 0;        // with fi = tid + i*256: ar = fi>>3
    const int ac4 = tid & 7;
    const int br  = tid >> 5;
    const int bc4 = tid & 31;

    float4 ra[4], rb[4];

    // prologue: load tile 0
#pragma unroll
    for (int i = 0; i < 4; ++i) {
        int fi = tid + i * 256;
        ra[i] = *(const float4*)&Ab[(size_t)(fi >> 3) * K + (fi & 7) * 4];
        rb[i] = *(const float4*)&Bb[(size_t)(fi >> 5) * N + (fi & 31) * 4];
    }
#pragma unroll
    for (int i = 0; i < 4; ++i) {
        int fi = tid + i * 256;
        *(uint4*)&(*As)[fi >> 3][(fi & 7) * 4] =
            make_uint4(f2tf32(ra[i].x), f2tf32(ra[i].y), f2tf32(ra[i].z), f2tf32(ra[i].w));
        *(uint4*)&(*Bs)[fi >> 5][(fi & 31) * 4] =
            make_uint4(f2tf32(rb[i].x), f2tf32(rb[i].y), f2tf32(rb[i].z), f2tf32(rb[i].w));
    }
    __syncthreads();

    float acc[2][8][4];
#pragma unroll
    for (int mi = 0; mi < 2; ++mi)
#pragma unroll
        for (int ni = 0; ni < 8; ++ni)
#pragma unroll
            for (int r = 0; r < 4; ++r) acc[mi][ni][r] = 0.f;

    int buf = 0;
    for (int kt = 32; kt <= K; kt += 32) {
        // prefetch next tile (if any)
        if (kt < K) {
#pragma unroll
            for (int i = 0; i < 4; ++i) {
                int fi = tid + i * 256;
                ra[i] = *(const float4*)&Ab[(size_t)(fi >> 3) * K + kt + (fi & 7) * 4];
                rb[i] = *(const float4*)&Bb[(size_t)(kt + (fi >> 5)) * N + (fi & 31) * 4];
            }
        }
        // compute on current buffer
#pragma unroll
        for (int kk = 0; kk < 32; kk += 8) {
            uint32_t af[2][4];
#pragma unroll
            for (int mi = 0; mi < 2; ++mi) {
                int mrow = wm0 + mi * 16 + group;
                af[mi][0] = As[buf][mrow][kk + tig];
                af[mi][1] = As[buf][mrow + 8][kk + tig];
                af[mi][2] = As[buf][mrow][kk + tig + 4];
                af[mi][3] = As[buf][mrow + 8][kk + tig + 4];
            }
#pragma unroll
            for (int ni = 0; ni < 8; ++ni) {
                uint32_t b0 = Bs[buf][kk + tig][wn0 + ni * 8 + group];
                uint32_t b1 = Bs[buf][kk + tig + 4][wn0 + ni * 8 + group];
                mma_tf32(acc[0][ni], af[0], b0, b1);
                mma_tf32(acc[1][ni], af[1], b0, b1);
            }
        }
        // store next tile into other buffer
        if (kt < K) {
#pragma unroll
            for (int i = 0; i < 4; ++i) {
                int fi = tid + i * 256;
                *(uint4*)&As[buf ^ 1][fi >> 3][(fi & 7) * 4] =
                    make_uint4(f2tf32(ra[i].x), f2tf32(ra[i].y), f2tf32(ra[i].z), f2tf32(ra[i].w));
                *(uint4*)&Bs[buf ^ 1][fi >> 5][(fi & 31) * 4] =
                    make_uint4(f2tf32(rb[i].x), f2tf32(rb[i].y), f2tf32(rb[i].z), f2tf32(rb[i].w));
            }
            __syncthreads();
            buf ^= 1;
        }
    }

    // epilogue
    const int base_m = blockIdx.y * 128 + wm0;
    const int base_n = blockIdx.x * 128 + wn0;
#pragma unroll
    for (int mi = 0; mi < 2; ++mi) {
#pragma unroll
        for (int rr = 0; rr < 2; ++rr) {
            int row = base_m + mi * 16 + rr * 8 + group;
#pragma unroll
            for (int ni = 0; ni < 8; ++ni) {
                int col = base_n + ni * 8 + tig * 2;
                float v0 = acc[mi][ni][rr * 2 + 0];
                float v1 = acc[mi][ni][rr * 2 + 1];
                if (HAS_BIAS) { v0 += bias[col]; v1 += bias[col + 1]; }
                if (DO_GELU) {
                    v0 = 0.5f * v0 * (1.0f + erff(v0 * 0.70710678118654752f));
                    v1 = 0.5f * v1 * (1.0f + erff(v1 * 0.70710678118654752f));
                }
                float* p = C + (size_t)row * N + col;
                if (RESID) {
                    float2 r = *(float2*)p;
                    v0 += r.x; v1 += r.y;
                }
                *(float2*)p = make_float2(v0, v1);
            }
        }
    }
}

// ---------------- TF32 tensor-core flash attention ----------------------------
// grid: (SEQ/64, NB*HEADS), block 128 (4 warps), each warp owns 16 Q rows.
// Dynamic smem: Ks[64][68] + Vs[64][68] + Ps[64][68] (uint32 tf32).
#define ATT_STRIDE 68
#define ATT_SMEM_WORDS (3 * 64 * ATT_STRIDE)
#define ATT_SMEM_BYTES (ATT_SMEM_WORDS * 4)

__global__ __launch_bounds__(128, 4) void attention_kernel(
    const float* __restrict__ qkv, float* __restrict__ out) {
    extern __shared__ uint32_t smem[];
    typedef uint32_t Tile[64][ATT_STRIDE];
    Tile& Ks = *(Tile*)smem;
    Tile& Vs = *(Tile*)(smem + 64 * ATT_STRIDE);
    Tile& Ps = *(Tile*)(smem + 2 * 64 * ATT_STRIDE);  // also used for Q staging

    const int tid  = threadIdx.x;
    const int lane = tid & 31;
    const int w    = tid >> 5;           // warp 0..3
    const int g    = lane >> 2;          // 0..7
    const int t    = lane & 3;           // 0..3

    const int bh = blockIdx.y;
    const int b  = bh / HEADS;
    const int h  = bh % HEADS;
    const int q0 = blockIdx.x * 64;      // CTA's first q row

    const float* qbase = qkv + ((size_t)(b * SEQ + q0)) * (3 * DIM) + h * DH;

    // ---- stage Q (scaled, tf32) into Ps region, then load A-fragments -------
#pragma unroll
    for (int f = 0; f < 8; ++f) {
        int idx = f * 128 + tid;             // 0..1023 float4 ids
        int r = idx >> 4;
        int c = (idx & 15) << 2;
        float4 v = *(const float4*)&qbase[(size_t)r * (3 * DIM) + c];
        *(uint4*)&Ps[r][c] = make_uint4(f2tf32(v.x * 0.125f), f2tf32(v.y * 0.125f),
                                        f2tf32(v.z * 0.125f), f2tf32(v.w * 0.125f));
    }
    __syncthreads();
    uint32_t qa[8][4];
    const int wr = w * 16;
#pragma unroll
    for (int kc = 0; kc < 8; ++kc) {
        qa[kc][0] = Ps[wr + g][kc * 8 + t];
        qa[kc][1] = Ps[wr + g + 8][kc * 8 + t];
        qa[kc][2] = Ps[wr + g][kc * 8 + t + 4];
        qa[kc][3] = Ps[wr + g + 8][kc * 8 + t + 4];
    }

    float m0 = -1e30f, m1 = -1e30f, l0 = 0.f, l1 = 0.f;
    float o[8][4];
#pragma unroll
    for (int ni = 0; ni < 8; ++ni)
#pragma unroll
        for (int r = 0; r < 4; ++r) o[ni][r] = 0.f;

    const float* kbase = qkv + ((size_t)(b * SEQ)) * (3 * DIM) + DIM + h * DH;
    const float* vbase = kbase + DIM;

    for (int jt = 0; jt < SEQ / 64; ++jt) {
        __syncthreads();   // prior iteration done reading Ks/Vs (iter0: Q frags done)
#pragma unroll
        for (int f = 0; f < 8; ++f) {
            int idx = f * 128 + tid;
            int r = idx >> 4;
            int c = (idx & 15) << 2;
            size_t off = (size_t)(jt * 64 + r) * (3 * DIM) + c;
            float4 kv = *(const float4*)&kbase[off];
            float4 vv = *(const float4*)&vbase[off];
            *(uint4*)&Ks[r][c] = make_uint4(f2tf32(kv.x), f2tf32(kv.y),
                                            f2tf32(kv.z), f2tf32(kv.w));
            *(uint4*)&Vs[r][c] = make_uint4(f2tf32(vv.x), f2tf32(vv.y),
                                            f2tf32(vv.z), f2tf32(vv.w));
        }
        __syncthreads();

        // ---- S = Q K^T : warp computes [16 x 64] ----
        float s[8][4];
#pragma unroll
        for (int ni = 0; ni < 8; ++ni)
#pragma unroll
            for (int r = 0; r < 4; ++r) s[ni][r] = 0.f;
#pragma unroll
        for (int kk = 0; kk < 8; ++kk) {
#pragma unroll
            for (int ni = 0; ni < 8; ++ni) {
                uint32_t b0 = Ks[ni * 8 + g][kk * 8 + t];
                uint32_t b1 = Ks[ni * 8 + g][kk * 8 + t + 4];
                mma_tf32(s[ni], qa[kk], b0, b1);
            }
        }

        // ---- online softmax on fragments ----
        float rmax0 = -1e30f, rmax1 = -1e30f;
#pragma unroll
        for (int ni = 0; ni < 8; ++ni) {
            rmax0 = fmaxf(rmax0, fmaxf(s[ni][0], s[ni][1]));
            rmax1 = fmaxf(rmax1, fmaxf(s[ni][2], s[ni][3]));
        }
#pragma unroll
        for (int ofs = 1; ofs <= 2; ofs <<= 1) {
            rmax0 = fmaxf(rmax0, __shfl_xor_sync(0xffffffffu, rmax0, ofs));
            rmax1 = fmaxf(rmax1, __shfl_xor_sync(0xffffffffu, rmax1, ofs));
        }
        float mn0 = fmaxf(m0, rmax0), mn1 = fmaxf(m1, rmax1);
        float corr0 = __expf(m0 - mn0), corr1 = __expf(m1 - mn1);
        m0 = mn0; m1 = mn1;
        float ps0 = 0.f, ps1 = 0.f;
#pragma unroll
        for (int ni = 0; ni < 8; ++ni) {
            float p0 = __expf(s[ni][0] - m0);
            float p1 = __expf(s[ni][1] - m0);
            float p2 = __expf(s[ni][2] - m1);
            float p3 = __expf(s[ni][3] - m1);
            ps0 += p0 + p1; ps1 += p2 + p3;
            // write P (tf32) to smem in accumulator layout
            *(uint2*)&Ps[wr + g][ni * 8 + 2 * t]     = make_uint2(f2tf32(p0), f2tf32(p1));
            *(uint2*)&Ps[wr + g + 8][ni * 8 + 2 * t] = make_uint2(f2tf32(p2), f2tf32(p3));
        }
#pragma unroll
        for (int ofs = 1; ofs <= 2; ofs <<= 1) {
            ps0 += __shfl_xor_sync(0xffffffffu, ps0, ofs);
            ps1 += __shfl_xor_sync(0xffffffffu, ps1, ofs);
        }
        l0 = l0 * corr0 + ps0;
        l1 = l1 * corr1 + ps1;
#pragma unroll
        for (int ni = 0; ni < 8; ++ni) {
            o[ni][0] *= corr0; o[ni][1] *= corr0;
            o[ni][2] *= corr1; o[ni][3] *= corr1;
        }
        __syncwarp();

        // ---- O += P V : warp computes [16 x 64] ----
#pragma unroll
        for (int kk = 0; kk < 8; ++kk) {
            uint32_t pa[4];
            pa[0] = Ps[wr + g][kk * 8 + t];
            pa[1] = Ps[wr + g + 8][kk * 8 + t];
            pa[2] = Ps[wr + g][kk * 8 + t + 4];
            pa[3] = Ps[wr + g + 8][kk * 8 + t + 4];
#pragma unroll
            for (int ni = 0; ni < 8; ++ni) {
                uint32_t b0 = Vs[kk * 8 + t][ni * 8 + g];
                uint32_t b1 = Vs[kk * 8 + t + 4][ni * 8 + g];
                mma_tf32(o[ni], pa, b0, b1);
            }
        }
    }

    // ---- epilogue ----
    float inv0 = 1.0f / l0, inv1 = 1.0f / l1;
    const int row0 = q0 + wr + g;
    const int row1 = row0 + 8;
    float* ob0 = out + (size_t)(b * SEQ + row0) * DIM + h * DH;
    float* ob1 = out + (size_t)(b * SEQ + row1) * DIM + h * DH;
#pragma unroll
    for (int ni = 0; ni < 8; ++ni) {
        int c = ni * 8 + 2 * t;
        *(float2*)&ob0[c] = make_float2(o[ni][0] * inv0, o[ni][1] * inv0);
        *(float2*)&ob1[c] = make_float2(o[ni][2] * inv1, o[ni][3] * inv1);
    }
}

// ---------------- host side ---------------------------------------------------
extern "C" void kernel_launch(void* const* d_in, const int* in_sizes, int n_in,
                              void* d_out, int out_size) {
    const float* x      = (const float*)d_in[0];
    const float* ln1_w  = (const float*)d_in[1];
    const float* ln1_b  = (const float*)d_in[2];
    const float* w_qkv  = (const float*)d_in[3];
    const float* w_o    = (const float*)d_in[4];
    const float* b_o    = (const float*)d_in[5];
    const float* ln2_w  = (const float*)d_in[6];
    const float* ln2_b  = (const float*)d_in[7];
    const float* w1     = (const float*)d_in[8];
    const float* b1     = (const float*)d_in[9];
    const float* w2     = (const float*)d_in[10];
    const float* b2     = (const float*)d_in[11];

    float* X = (float*)d_out;

    float *pH, *pQKV, *pATT, *pMLP;
    cudaGetSymbolAddress((void**)&pH,   g_h);
    cudaGetSymbolAddress((void**)&pQKV, g_qkv);
    cudaGetSymbolAddress((void**)&pATT, g_attn);
    cudaGetSymbolAddress((void**)&pMLP, g_mlp);

    // raise dynamic smem limits (idempotent, not a stream op)
    cudaFuncSetAttribute(tf32_gemm_kernel<false, false, false>,
                         cudaFuncAttributeMaxDynamicSharedMemorySize, GEMM_SMEM_BYTES);
    cudaFuncSetAttribute(tf32_gemm_kernel<true, true, false>,
                         cudaFuncAttributeMaxDynamicSharedMemorySize, GEMM_SMEM_BYTES);
    cudaFuncSetAttribute(tf32_gemm_kernel<true, false, true>,
                         cudaFuncAttributeMaxDynamicSharedMemorySize, GEMM_SMEM_BYTES);
    cudaFuncSetAttribute(attention_kernel,
                         cudaFuncAttributeMaxDynamicSharedMemorySize, ATT_SMEM_BYTES);

    cudaMemcpyAsync(X, x, (size_t)TOK * DIM * sizeof(float),
                    cudaMemcpyDeviceToDevice);

    for (int l = 0; l < 6; ++l) {
        const float* l1w = ln1_w + l * DIM;
        const float* l1b = ln1_b + l * DIM;
        const float* wqkv = w_qkv + (size_t)l * DIM * 3 * DIM;
        const float* wo   = w_o   + (size_t)l * DIM * DIM;
        const float* bo   = b_o   + l * DIM;
        const float* l2w = ln2_w + l * DIM;
        const float* l2b = ln2_b + l * DIM;
        const float* W1 = w1 + (size_t)l * DIM * MLPD;
        const float* B1 = b1 + l * MLPD;
        const float* W2 = w2 + (size_t)l * MLPD * DIM;
        const float* B2 = b2 + l * DIM;

        // LN1
        layernorm_kernel<<<TOK, 256>>>(X, l1w, l1b, pH);
        // QKV: [4096,768] @ [768,2304]  (no bias)
        tf32_gemm_kernel<false, false, false>
            <<<dim3(3 * DIM / 128, TOK / 128), 256, GEMM_SMEM_BYTES>>>(
                pH, wqkv, nullptr, pQKV, TOK, 3 * DIM, DIM);
        // fused tensor-core attention
        attention_kernel<<<dim3(SEQ / 64, NB * HEADS), 128, ATT_SMEM_BYTES>>>(pQKV, pATT);
        // O-proj + bias + residual into X
        tf32_gemm_kernel<true, true, false>
            <<<dim3(DIM / 128, TOK / 128), 256, GEMM_SMEM_BYTES>>>(
                pATT, wo, bo, X, TOK, DIM, DIM);
        // LN2
        layernorm_kernel<<<TOK, 256>>>(X, l2w, l2b, pH);
        // MLP1 + bias + exact GELU
        tf32_gemm_kernel<true, false, true>
            <<<dim3(MLPD / 128, TOK / 128), 256, GEMM_SMEM_BYTES>>>(
                pH, W1, B1, pMLP, TOK, MLPD, DIM);
        // MLP2 + bias + residual into X
        tf32_gemm_kernel<true, true, false>
            <<<dim3(DIM / 128, TOK / 128), 256, GEMM_SMEM_BYTES>>>(
                pMLP, W2, B2, X, TOK, DIM, MLPD);
    }
}

// round 6
// speedup vs baseline: 2.1061x; 1.0955x over previous
#include <cuda_runtime.h>
#include <math.h>
#include <stdint.h>

#define DIM 768
#define MLPD 3072
#define HEADS 12
#define DH 64
#define TOK 4096          // 4 * 1024
#define SEQ 1024
#define NB 4

// ---------------- scratch buffers (device globals; no allocation allowed) ----
__device__ uint32_t g_h[TOK * DIM];        // LN output (tf32)
__device__ float    g_qkv[TOK * 3 * DIM];  // qkv projections (fp32)
__device__ uint32_t g_attn[TOK * DIM];     // attention output (tf32)
__device__ uint32_t g_mlp[TOK * MLPD];     // MLP hidden (tf32)

// tf32 weight copies (converted once per launch)
__device__ uint32_t g_wqkv_t[6 * DIM * 3 * DIM];
__device__ uint32_t g_wo_t[6 * DIM * DIM];
__device__ uint32_t g_w1_t[6 * DIM * MLPD];
__device__ uint32_t g_w2_t[6 * MLPD * DIM];

// ---------------- helpers ------------------------------------------------------
__device__ __forceinline__ uint32_t f2tf32(float f) {
    uint32_t u;
    asm("cvt.rna.tf32.f32 %0, %1;" : "=r"(u) : "f"(f));
    return u;
}

__device__ __forceinline__ void mma_tf32(float c[4], const uint32_t a[4],
                                         uint32_t b0, uint32_t b1) {
    asm volatile(
        "mma.sync.aligned.m16n8k8.row.col.f32.tf32.tf32.f32 "
        "{%0,%1,%2,%3}, {%4,%5,%6,%7}, {%8,%9}, {%0,%1,%2,%3};"
        : "+f"(c[0]), "+f"(c[1]), "+f"(c[2]), "+f"(c[3])
        : "r"(a[0]), "r"(a[1]), "r"(a[2]), "r"(a[3]), "r"(b0), "r"(b1));
}

__device__ __forceinline__ void cp_async16(uint32_t saddr, const void* gptr) {
    asm volatile("cp.async.cg.shared.global [%0], [%1], 16;"
                 :: "r"(saddr), "l"(gptr));
}
__device__ __forceinline__ void cp_commit() {
    asm volatile("cp.async.commit_group;");
}

// ---------------- fp32 -> tf32 bulk convert (weights) -------------------------
__global__ void cvt_tf32_kernel(const float* __restrict__ in,
                                uint32_t* __restrict__ out) {
    int i = (blockIdx.x * 256 + threadIdx.x) * 4;
    float4 v = *(const float4*)&in[i];
    *(uint4*)&out[i] = make_uint4(f2tf32(v.x), f2tf32(v.y),
                                  f2tf32(v.z), f2tf32(v.w));
}

// ---------------- LayerNorm: one block per row, writes tf32 -------------------
__global__ void layernorm_kernel(const float* __restrict__ x,
                                 const float* __restrict__ w,
                                 const float* __restrict__ b,
                                 uint32_t* __restrict__ out) {
    int row = blockIdx.x;
    const float* xr = x + (size_t)row * DIM;
    float vals[3];
    float s = 0.f, ss = 0.f;
#pragma unroll
    for (int i = 0; i < 3; ++i) {
        float v = xr[threadIdx.x + 256 * i];
        vals[i] = v;
        s += v;
        ss += v * v;
    }
#pragma unroll
    for (int o = 16; o; o >>= 1) {
        s  += __shfl_xor_sync(0xffffffffu, s, o);
        ss += __shfl_xor_sync(0xffffffffu, ss, o);
    }
    __shared__ float shs[8], shss[8];
    __shared__ float mean_s, rstd_s;
    int wid = threadIdx.x >> 5, lid = threadIdx.x & 31;
    if (lid == 0) { shs[wid] = s; shss[wid] = ss; }
    __syncthreads();
    if (threadIdx.x == 0) {
        float S = 0.f, SS = 0.f;
#pragma unroll
        for (int i = 0; i < 8; ++i) { S += shs[i]; SS += shss[i]; }
        float mean = S * (1.0f / DIM);
        float var  = SS * (1.0f / DIM) - mean * mean;
        mean_s = mean;
        rstd_s = rsqrtf(var + 1e-5f);
    }
    __syncthreads();
    float mean = mean_s, rstd = rstd_s;
    uint32_t* orow = out + (size_t)row * DIM;
#pragma unroll
    for (int i = 0; i < 3; ++i) {
        int idx = threadIdx.x + 256 * i;
        orow[idx] = f2tf32((vals[i] - mean) * rstd * w[idx] + b[idx]);
    }
}

// ---------------- TF32 tensor-core GEMM, 3-stage cp.async ---------------------
// C[M,N] = op( A[M,K] @ B[K,N] + bias ) (+ residual)
// A, B are pre-converted tf32 (uint32). block tile 128x128, K-tile 32,
// 8 warps (4x2), warp tile 32x64.
#define STAGES 3
#define AS_W (128 * 36)
#define BS_W (32 * 136)
#define GEMM_SMEM_BYTES (STAGES * (AS_W + BS_W) * 4)

template <bool HAS_BIAS, bool RESID, bool DO_GELU, bool OUT_TF32>
__global__ __launch_bounds__(256, 2) void tf32_gemm_kernel(
    const uint32_t* __restrict__ A, const uint32_t* __restrict__ B,
    const float* __restrict__ bias, void* __restrict__ Cv,
    int M, int N, int K) {
    extern __shared__ uint32_t smem[];

    const int tid   = threadIdx.x;
    const int lane  = tid & 31;
    const int wid   = tid >> 5;
    const int group = lane >> 2;   // 0..7
    const int tig   = lane & 3;    // 0..3
    const int wm0   = (wid >> 1) * 32;  // warp row offset 0..96
    const int wn0   = (wid & 1) * 64;   // warp col offset 0/64

    const uint32_t* Ab = A + (size_t)(blockIdx.y * 128) * K;
    const uint32_t* Bb = B + (size_t)(blockIdx.x * 128);

    const uint32_t smem_base = (uint32_t)__cvta_generic_to_shared(smem);

    // per-thread load coordinates
    const int ar  = tid >> 3;     // base A row for fi = tid (+ i*256 adds 32 rows)
    const int ac4 = tid & 7;
    const int br  = tid >> 5;     // base B row (+ i*256 adds 8 rows)
    const int bc4 = tid & 31;

    const int T = K / 32;

#define ISSUE_TILE(kt, s)                                                      \
    do {                                                                       \
        _Pragma("unroll")                                                      \
        for (int i = 0; i < 4; ++i) {                                          \
            uint32_t da = smem_base +                                          \
                ((s) * AS_W + (ar + i * 32) * 36 + ac4 * 4) * 4;               \
            cp_async16(da, Ab + (size_t)(ar + i * 32) * K + (kt) + ac4 * 4);   \
            uint32_t db = smem_base +                                          \
                (STAGES * AS_W + (s) * BS_W + (br + i * 8) * 136 + bc4 * 4) * 4;\
            cp_async16(db, Bb + (size_t)((kt) + br + i * 8) * N + bc4 * 4);    \
        }                                                                      \
        cp_commit();                                                           \
    } while (0)

    ISSUE_TILE(0, 0);
    ISSUE_TILE(32, 1);

    float acc[2][8][4];
#pragma unroll
    for (int mi = 0; mi < 2; ++mi)
#pragma unroll
        for (int ni = 0; ni < 8; ++ni)
#pragma unroll
            for (int r = 0; r < 4; ++r) acc[mi][ni][r] = 0.f;

    for (int it = 0; it < T; ++it) {
        asm volatile("cp.async.wait_group 1;");
        __syncthreads();
        if (it + 2 < T) {
            int s = (it + 2) % STAGES;
            ISSUE_TILE((it + 2) * 32, s);
        }
        const int sb = it % STAGES;
        const uint32_t* Asb = smem + sb * AS_W;
        const uint32_t* Bsb = smem + STAGES * AS_W + sb * BS_W;

#pragma unroll
        for (int kk = 0; kk < 32; kk += 8) {
            uint32_t af[2][4];
#pragma unroll
            for (int mi = 0; mi < 2; ++mi) {
                int mrow = wm0 + mi * 16 + group;
                af[mi][0] = Asb[mrow * 36 + kk + tig];
                af[mi][1] = Asb[(mrow + 8) * 36 + kk + tig];
                af[mi][2] = Asb[mrow * 36 + kk + tig + 4];
                af[mi][3] = Asb[(mrow + 8) * 36 + kk + tig + 4];
            }
#pragma unroll
            for (int ni = 0; ni < 8; ++ni) {
                uint32_t b0 = Bsb[(kk + tig) * 136 + wn0 + ni * 8 + group];
                uint32_t b1 = Bsb[(kk + tig + 4) * 136 + wn0 + ni * 8 + group];
                mma_tf32(acc[0][ni], af[0], b0, b1);
                mma_tf32(acc[1][ni], af[1], b0, b1);
            }
        }
    }
#undef ISSUE_TILE

    // epilogue
    const int base_m = blockIdx.y * 128 + wm0;
    const int base_n = blockIdx.x * 128 + wn0;
#pragma unroll
    for (int mi = 0; mi < 2; ++mi) {
#pragma unroll
        for (int rr = 0; rr < 2; ++rr) {
            int row = base_m + mi * 16 + rr * 8 + group;
#pragma unroll
            for (int ni = 0; ni < 8; ++ni) {
                int col = base_n + ni * 8 + tig * 2;
                float v0 = acc[mi][ni][rr * 2 + 0];
                float v1 = acc[mi][ni][rr * 2 + 1];
                if (HAS_BIAS) { v0 += bias[col]; v1 += bias[col + 1]; }
                if (DO_GELU) {
                    v0 = 0.5f * v0 * (1.0f + erff(v0 * 0.70710678118654752f));
                    v1 = 0.5f * v1 * (1.0f + erff(v1 * 0.70710678118654752f));
                }
                if (OUT_TF32) {
                    uint32_t* p = (uint32_t*)Cv + (size_t)row * N + col;
                    *(uint2*)p = make_uint2(f2tf32(v0), f2tf32(v1));
                } else {
                    float* p = (float*)Cv + (size_t)row * N + col;
                    if (RESID) {
                        float2 r = *(float2*)p;
                        v0 += r.x; v1 += r.y;
                    }
                    *(float2*)p = make_float2(v0, v1);
                }
            }
        }
    }
}

// ---------------- TF32 tensor-core flash attention ----------------------------
// grid: (SEQ/64, NB*HEADS), block 128 (4 warps), each warp owns 16 Q rows.
// Output written as tf32 (feeds O-projection GEMM directly).
#define ATT_STRIDE 68
#define ATT_SMEM_WORDS (3 * 64 * ATT_STRIDE)
#define ATT_SMEM_BYTES (ATT_SMEM_WORDS * 4)

__global__ __launch_bounds__(128, 4) void attention_kernel(
    const float* __restrict__ qkv, uint32_t* __restrict__ out) {
    extern __shared__ uint32_t smem[];
    typedef uint32_t Tile[64][ATT_STRIDE];
    Tile& Ks = *(Tile*)smem;
    Tile& Vs = *(Tile*)(smem + 64 * ATT_STRIDE);
    Tile& Ps = *(Tile*)(smem + 2 * 64 * ATT_STRIDE);  // also used for Q staging

    const int tid  = threadIdx.x;
    const int lane = tid & 31;
    const int w    = tid >> 5;           // warp 0..3
    const int g    = lane >> 2;          // 0..7
    const int t    = lane & 3;           // 0..3

    const int bh = blockIdx.y;
    const int b  = bh / HEADS;
    const int h  = bh % HEADS;
    const int q0 = blockIdx.x * 64;      // CTA's first q row

    const float* qbase = qkv + ((size_t)(b * SEQ + q0)) * (3 * DIM) + h * DH;

    // ---- stage Q (scaled, tf32) into Ps region, then load A-fragments -------
#pragma unroll
    for (int f = 0; f < 8; ++f) {
        int idx = f * 128 + tid;             // 0..1023 float4 ids
        int r = idx >> 4;
        int c = (idx & 15) << 2;
        float4 v = *(const float4*)&qbase[(size_t)r * (3 * DIM) + c];
        *(uint4*)&Ps[r][c] = make_uint4(f2tf32(v.x * 0.125f), f2tf32(v.y * 0.125f),
                                        f2tf32(v.z * 0.125f), f2tf32(v.w * 0.125f));
    }
    __syncthreads();
    uint32_t qa[8][4];
    const int wr = w * 16;
#pragma unroll
    for (int kc = 0; kc < 8; ++kc) {
        qa[kc][0] = Ps[wr + g][kc * 8 + t];
        qa[kc][1] = Ps[wr + g + 8][kc * 8 + t];
        qa[kc][2] = Ps[wr + g][kc * 8 + t + 4];
        qa[kc][3] = Ps[wr + g + 8][kc * 8 + t + 4];
    }

    float m0 = -1e30f, m1 = -1e30f, l0 = 0.f, l1 = 0.f;
    float o[8][4];
#pragma unroll
    for (int ni = 0; ni < 8; ++ni)
#pragma unroll
        for (int r = 0; r < 4; ++r) o[ni][r] = 0.f;

    const float* kbase = qkv + ((size_t)(b * SEQ)) * (3 * DIM) + DIM + h * DH;
    const float* vbase = kbase + DIM;

    for (int jt = 0; jt < SEQ / 64; ++jt) {
        __syncthreads();   // prior iteration done reading Ks/Vs (iter0: Q frags done)
#pragma unroll
        for (int f = 0; f < 8; ++f) {
            int idx = f * 128 + tid;
            int r = idx >> 4;
            int c = (idx & 15) << 2;
            size_t off = (size_t)(jt * 64 + r) * (3 * DIM) + c;
            float4 kv = *(const float4*)&kbase[off];
            float4 vv = *(const float4*)&vbase[off];
            *(uint4*)&Ks[r][c] = make_uint4(f2tf32(kv.x), f2tf32(kv.y),
                                            f2tf32(kv.z), f2tf32(kv.w));
            *(uint4*)&Vs[r][c] = make_uint4(f2tf32(vv.x), f2tf32(vv.y),
                                            f2tf32(vv.z), f2tf32(vv.w));
        }
        __syncthreads();

        // ---- S = Q K^T : warp computes [16 x 64] ----
        float s[8][4];
#pragma unroll
        for (int ni = 0; ni < 8; ++ni)
#pragma unroll
            for (int r = 0; r < 4; ++r) s[ni][r] = 0.f;
#pragma unroll
        for (int kk = 0; kk < 8; ++kk) {
#pragma unroll
            for (int ni = 0; ni < 8; ++ni) {
                uint32_t b0 = Ks[ni * 8 + g][kk * 8 + t];
                uint32_t b1 = Ks[ni * 8 + g][kk * 8 + t + 4];
                mma_tf32(s[ni], qa[kk], b0, b1);
            }
        }

        // ---- online softmax on fragments ----
        float rmax0 = -1e30f, rmax1 = -1e30f;
#pragma unroll
        for (int ni = 0; ni < 8; ++ni) {
            rmax0 = fmaxf(rmax0, fmaxf(s[ni][0], s[ni][1]));
            rmax1 = fmaxf(rmax1, fmaxf(s[ni][2], s[ni][3]));
        }
#pragma unroll
        for (int ofs = 1; ofs <= 2; ofs <<= 1) {
            rmax0 = fmaxf(rmax0, __shfl_xor_sync(0xffffffffu, rmax0, ofs));
            rmax1 = fmaxf(rmax1, __shfl_xor_sync(0xffffffffu, rmax1, ofs));
        }
        float mn0 = fmaxf(m0, rmax0), mn1 = fmaxf(m1, rmax1);
        float corr0 = __expf(m0 - mn0), corr1 = __expf(m1 - mn1);
        m0 = mn0; m1 = mn1;
        float ps0 = 0.f, ps1 = 0.f;
#pragma unroll
        for (int ni = 0; ni < 8; ++ni) {
            float p0 = __expf(s[ni][0] - m0);
            float p1 = __expf(s[ni][1] - m0);
            float p2 = __expf(s[ni][2] - m1);
            float p3 = __expf(s[ni][3] - m1);
            ps0 += p0 + p1; ps1 += p2 + p3;
            // write P (tf32) to smem in accumulator layout
            *(uint2*)&Ps[wr + g][ni * 8 + 2 * t]     = make_uint2(f2tf32(p0), f2tf32(p1));
            *(uint2*)&Ps[wr + g + 8][ni * 8 + 2 * t] = make_uint2(f2tf32(p2), f2tf32(p3));
        }
#pragma unroll
        for (int ofs = 1; ofs <= 2; ofs <<= 1) {
            ps0 += __shfl_xor_sync(0xffffffffu, ps0, ofs);
            ps1 += __shfl_xor_sync(0xffffffffu, ps1, ofs);
        }
        l0 = l0 * corr0 + ps0;
        l1 = l1 * corr1 + ps1;
#pragma unroll
        for (int ni = 0; ni < 8; ++ni) {
            o[ni][0] *= corr0; o[ni][1] *= corr0;
            o[ni][2] *= corr1; o[ni][3] *= corr1;
        }
        __syncwarp();

        // ---- O += P V : warp computes [16 x 64] ----
#pragma unroll
        for (int kk = 0; kk < 8; ++kk) {
            uint32_t pa[4];
            pa[0] = Ps[wr + g][kk * 8 + t];
            pa[1] = Ps[wr + g + 8][kk * 8 + t];
            pa[2] = Ps[wr + g][kk * 8 + t + 4];
            pa[3] = Ps[wr + g + 8][kk * 8 + t + 4];
#pragma unroll
            for (int ni = 0; ni < 8; ++ni) {
                uint32_t b0 = Vs[kk * 8 + t][ni * 8 + g];
                uint32_t b1 = Vs[kk * 8 + t + 4][ni * 8 + g];
                mma_tf32(o[ni], pa, b0, b1);
            }
        }
    }

    // ---- epilogue (tf32 out) ----
    float inv0 = 1.0f / l0, inv1 = 1.0f / l1;
    const int row0 = q0 + wr + g;
    const int row1 = row0 + 8;
    uint32_t* ob0 = out + (size_t)(b * SEQ + row0) * DIM + h * DH;
    uint32_t* ob1 = out + (size_t)(b * SEQ + row1) * DIM + h * DH;
#pragma unroll
    for (int ni = 0; ni < 8; ++ni) {
        int c = ni * 8 + 2 * t;
        *(uint2*)&ob0[c] = make_uint2(f2tf32(o[ni][0] * inv0), f2tf32(o[ni][1] * inv0));
        *(uint2*)&ob1[c] = make_uint2(f2tf32(o[ni][2] * inv1), f2tf32(o[ni][3] * inv1));
    }
}

// ---------------- host side ---------------------------------------------------
extern "C" void kernel_launch(void* const* d_in, const int* in_sizes, int n_in,
                              void* d_out, int out_size) {
    const float* x      = (const float*)d_in[0];
    const float* ln1_w  = (const float*)d_in[1];
    const float* ln1_b  = (const float*)d_in[2];
    const float* w_qkv  = (const float*)d_in[3];
    const float* w_o    = (const float*)d_in[4];
    const float* b_o    = (const float*)d_in[5];
    const float* ln2_w  = (const float*)d_in[6];
    const float* ln2_b  = (const float*)d_in[7];
    const float* w1     = (const float*)d_in[8];
    const float* b1     = (const float*)d_in[9];
    const float* w2     = (const float*)d_in[10];
    const float* b2     = (const float*)d_in[11];

    float* X = (float*)d_out;

    uint32_t *pH, *pATT, *pMLP;
    float* pQKV;
    uint32_t *pWQKV, *pWO, *pW1, *pW2;
    cudaGetSymbolAddress((void**)&pH,    g_h);
    cudaGetSymbolAddress((void**)&pQKV,  g_qkv);
    cudaGetSymbolAddress((void**)&pATT,  g_attn);
    cudaGetSymbolAddress((void**)&pMLP,  g_mlp);
    cudaGetSymbolAddress((void**)&pWQKV, g_wqkv_t);
    cudaGetSymbolAddress((void**)&pWO,   g_wo_t);
    cudaGetSymbolAddress((void**)&pW1,   g_w1_t);
    cudaGetSymbolAddress((void**)&pW2,   g_w2_t);

    // raise dynamic smem limits (idempotent, not a stream op)
    cudaFuncSetAttribute(tf32_gemm_kernel<false, false, false, false>,
                         cudaFuncAttributeMaxDynamicSharedMemorySize, GEMM_SMEM_BYTES);
    cudaFuncSetAttribute(tf32_gemm_kernel<true, true, false, false>,
                         cudaFuncAttributeMaxDynamicSharedMemorySize, GEMM_SMEM_BYTES);
    cudaFuncSetAttribute(tf32_gemm_kernel<true, false, true, true>,
                         cudaFuncAttributeMaxDynamicSharedMemorySize, GEMM_SMEM_BYTES);
    cudaFuncSetAttribute(attention_kernel,
                         cudaFuncAttributeMaxDynamicSharedMemorySize, ATT_SMEM_BYTES);

    // convert all weights to tf32 once
    cvt_tf32_kernel<<<6 * DIM * 3 * DIM / 1024, 256>>>(w_qkv, pWQKV);
    cvt_tf32_kernel<<<6 * DIM * DIM / 1024, 256>>>(w_o, pWO);
    cvt_tf32_kernel<<<6 * DIM * MLPD / 1024, 256>>>(w1, pW1);
    cvt_tf32_kernel<<<6 * MLPD * DIM / 1024, 256>>>(w2, pW2);

    cudaMemcpyAsync(X, x, (size_t)TOK * DIM * sizeof(float),
                    cudaMemcpyDeviceToDevice);

    for (int l = 0; l < 6; ++l) {
        const float* l1w = ln1_w + l * DIM;
        const float* l1b = ln1_b + l * DIM;
        const float* bo  = b_o + l * DIM;
        const float* l2w = ln2_w + l * DIM;
        const float* l2b = ln2_b + l * DIM;
        const float* B1  = b1 + l * MLPD;
        const float* B2  = b2 + l * DIM;
        const uint32_t* wqkv = pWQKV + (size_t)l * DIM * 3 * DIM;
        const uint32_t* wo   = pWO   + (size_t)l * DIM * DIM;
        const uint32_t* W1   = pW1   + (size_t)l * DIM * MLPD;
        const uint32_t* W2   = pW2   + (size_t)l * MLPD * DIM;

        // LN1 -> tf32
        layernorm_kernel<<<TOK, 256>>>(X, l1w, l1b, pH);
        // QKV: [4096,768] @ [768,2304] -> fp32
        tf32_gemm_kernel<false, false, false, false>
            <<<dim3(3 * DIM / 128, TOK / 128), 256, GEMM_SMEM_BYTES>>>(
                pH, wqkv, nullptr, pQKV, TOK, 3 * DIM, DIM);
        // fused tensor-core attention -> tf32
        attention_kernel<<<dim3(SEQ / 64, NB * HEADS), 128, ATT_SMEM_BYTES>>>(pQKV, pATT);
        // O-proj + bias + residual into X (fp32)
        tf32_gemm_kernel<true, true, false, false>
            <<<dim3(DIM / 128, TOK / 128), 256, GEMM_SMEM_BYTES>>>(
                pATT, wo, bo, X, TOK, DIM, DIM);
        // LN2 -> tf32
        layernorm_kernel<<<TOK, 256>>>(X, l2w, l2b, pH);
        // MLP1 + bias + exact GELU -> tf32
        tf32_gemm_kernel<true, false, true, true>
            <<<dim3(MLPD / 128, TOK / 128), 256, GEMM_SMEM_BYTES>>>(
                pH, W1, B1, pMLP, TOK, MLPD, DIM);
        // MLP2 + bias + residual into X (fp32)
        tf32_gemm_kernel<true, true, false, false>
            <<<dim3(DIM / 128, TOK / 128), 256, GEMM_SMEM_BYTES>>>(
                pMLP, W2, B2, X, TOK, DIM, MLPD);
    }
}

// round 7
// speedup vs baseline: 2.2046x; 1.0468x over previous
#include <cuda_runtime.h>
#include <math.h>
#include <stdint.h>

#define DIM 768
#define MLPD 3072
#define HEADS 12
#define DH 64
#define TOK 4096          // 4 * 1024
#define SEQ 1024
#define NB 4

// ---------------- scratch buffers (device globals; no allocation allowed) ----
__device__ uint32_t g_h[TOK * DIM];        // LN output (tf32)
__device__ float    g_qkv[TOK * 3 * DIM];  // qkv projections (fp32)
__device__ uint32_t g_attn[TOK * DIM];     // attention output (tf32)
__device__ uint32_t g_mlp[TOK * MLPD];     // MLP hidden (tf32)

// tf32 weight copies, TRANSPOSED to [N][K] (converted once per launch)
__device__ uint32_t g_wqkv_t[6 * DIM * 3 * DIM];
__device__ uint32_t g_wo_t[6 * DIM * DIM];
__device__ uint32_t g_w1_t[6 * DIM * MLPD];
__device__ uint32_t g_w2_t[6 * MLPD * DIM];

// ---------------- helpers ------------------------------------------------------
__device__ __forceinline__ uint32_t f2tf32(float f) {
    uint32_t u;
    asm("cvt.rna.tf32.f32 %0, %1;" : "=r"(u) : "f"(f));
    return u;
}

__device__ __forceinline__ void mma_tf32(float c[4], const uint32_t a[4],
                                         uint32_t b0, uint32_t b1) {
    asm volatile(
        "mma.sync.aligned.m16n8k8.row.col.f32.tf32.tf32.f32 "
        "{%0,%1,%2,%3}, {%4,%5,%6,%7}, {%8,%9}, {%0,%1,%2,%3};"
        : "+f"(c[0]), "+f"(c[1]), "+f"(c[2]), "+f"(c[3])
        : "r"(a[0]), "r"(a[1]), "r"(a[2]), "r"(a[3]), "r"(b0), "r"(b1));
}

__device__ __forceinline__ void ldsm4(uint32_t r[4], uint32_t saddr) {
    asm volatile("ldmatrix.sync.aligned.m8n8.x4.shared.b16 {%0,%1,%2,%3}, [%4];"
                 : "=r"(r[0]), "=r"(r[1]), "=r"(r[2]), "=r"(r[3])
                 : "r"(saddr));
}

__device__ __forceinline__ void cp_async16(uint32_t saddr, const void* gptr) {
    asm volatile("cp.async.cg.shared.global [%0], [%1], 16;"
                 :: "r"(saddr), "l"(gptr));
}
__device__ __forceinline__ void cp_commit() {
    asm volatile("cp.async.commit_group;");
}

// ---------------- fp32 [K,N] -> tf32 [N,K] transpose-convert -----------------
// block (32,8); grid (N/32, K/32, layers)
__global__ void cvtT_kernel(const float* __restrict__ in,
                            uint32_t* __restrict__ out, int K, int N) {
    __shared__ uint32_t tile[32][33];
    const size_t lofs = (size_t)blockIdx.z * K * N;
    const float* inL = in + lofs;
    uint32_t* outL = out + lofs;
    int k0 = blockIdx.y * 32, n0 = blockIdx.x * 32;
#pragma unroll
    for (int i = threadIdx.y; i < 32; i += 8)
        tile[i][threadIdx.x] = f2tf32(inL[(size_t)(k0 + i) * N + n0 + threadIdx.x]);
    __syncthreads();
#pragma unroll
    for (int i = threadIdx.y; i < 32; i += 8)
        outL[(size_t)(n0 + i) * K + k0 + threadIdx.x] = tile[threadIdx.x][i];
}

// ---------------- LayerNorm: one block per row, writes tf32 -------------------
__global__ void layernorm_kernel(const float* __restrict__ x,
                                 const float* __restrict__ w,
                                 const float* __restrict__ b,
                                 uint32_t* __restrict__ out) {
    int row = blockIdx.x;
    const float* xr = x + (size_t)row * DIM;
    float vals[3];
    float s = 0.f, ss = 0.f;
#pragma unroll
    for (int i = 0; i < 3; ++i) {
        float v = xr[threadIdx.x + 256 * i];
        vals[i] = v;
        s += v;
        ss += v * v;
    }
#pragma unroll
    for (int o = 16; o; o >>= 1) {
        s  += __shfl_xor_sync(0xffffffffu, s, o);
        ss += __shfl_xor_sync(0xffffffffu, ss, o);
    }
    __shared__ float shs[8], shss[8];
    __shared__ float mean_s, rstd_s;
    int wid = threadIdx.x >> 5, lid = threadIdx.x & 31;
    if (lid == 0) { shs[wid] = s; shss[wid] = ss; }
    __syncthreads();
    if (threadIdx.x == 0) {
        float S = 0.f, SS = 0.f;
#pragma unroll
        for (int i = 0; i < 8; ++i) { S += shs[i]; SS += shss[i]; }
        float mean = S * (1.0f / DIM);
        float var  = SS * (1.0f / DIM) - mean * mean;
        mean_s = mean;
        rstd_s = rsqrtf(var + 1e-5f);
    }
    __syncthreads();
    float mean = mean_s, rstd = rstd_s;
    uint32_t* orow = out + (size_t)row * DIM;
#pragma unroll
    for (int i = 0; i < 3; ++i) {
        int idx = threadIdx.x + 256 * i;
        orow[idx] = f2tf32((vals[i] - mean) * rstd * w[idx] + b[idx]);
    }
}

// ---------------- TF32 tensor-core GEMM, 3-stage cp.async + ldmatrix ----------
// C[M,N] = op( A[M,K] @ B^T + bias ) (+ residual), B given as [N][K] tf32.
// block tile 128x128, K-tile 32, 8 warps (4x2), warp tile 32x64.
#define STAGES 3
#define AS_W (128 * 36)
#define BS_W (128 * 36)
#define GEMM_SMEM_BYTES (STAGES * (AS_W + BS_W) * 4)

template <bool HAS_BIAS, bool RESID, bool DO_GELU, bool OUT_TF32>
__global__ __launch_bounds__(256, 2) void tf32_gemm_kernel(
    const uint32_t* __restrict__ A, const uint32_t* __restrict__ B,
    const float* __restrict__ bias, void* __restrict__ Cv,
    int M, int N, int K) {
    extern __shared__ uint32_t smem[];

    const int tid   = threadIdx.x;
    const int lane  = tid & 31;
    const int wid   = tid >> 5;
    const int group = lane >> 2;   // 0..7
    const int tig   = lane & 3;    // 0..3
    const int wm0   = (wid >> 1) * 32;  // warp row offset 0..96
    const int wn0   = (wid & 1) * 64;   // warp col offset 0/64

    const uint32_t* Ab = A + (size_t)(blockIdx.y * 128) * K;
    const uint32_t* Bb = B + (size_t)(blockIdx.x * 128) * K;  // [N][K]

    const uint32_t smem_base = (uint32_t)__cvta_generic_to_shared(smem);

    // per-thread cp.async coordinates (rows of 32 words = 8 float4)
    const int lr  = tid >> 3;     // base row (+ i*32)
    const int lc4 = tid & 7;      // float4 within row

    // ldmatrix per-lane address offsets (bytes, within a stage buffer)
    //   A: row = wm0 + (lane&7) + ((lane&8)?8:0), col = ((lane&16)?4:0)
    const uint32_t a_off =
        ((uint32_t)(wm0 + (lane & 7) + ((lane >> 3) & 1) * 8) * 36 +
         (uint32_t)((lane >> 4) & 1) * 4) * 4;
    //   B: row = wn0 + (lane&7) + ((lane&16)?8:0), col = ((lane&8)?4:0)
    const uint32_t b_off =
        ((uint32_t)(wn0 + (lane & 7) + ((lane >> 4) & 1) * 8) * 36 +
         (uint32_t)((lane >> 3) & 1) * 4) * 4;

    const int T = K / 32;

#define ISSUE_TILE(kt, s)                                                       \
    do {                                                                        \
        _Pragma("unroll")                                                       \
        for (int i = 0; i < 4; ++i) {                                           \
            uint32_t da = smem_base +                                           \
                ((s) * AS_W + (lr + i * 32) * 36 + lc4 * 4) * 4;                \
            cp_async16(da, Ab + (size_t)(lr + i * 32) * K + (kt) + lc4 * 4);    \
            uint32_t db = smem_base +                                           \
                (STAGES * AS_W + (s) * BS_W + (lr + i * 32) * 36 + lc4 * 4) * 4;\
            cp_async16(db, Bb + (size_t)(lr + i * 32) * K + (kt) + lc4 * 4);    \
        }                                                                       \
        cp_commit();                                                            \
    } while (0)

    ISSUE_TILE(0, 0);
    ISSUE_TILE(32, 1);

    float acc[2][8][4];
#pragma unroll
    for (int mi = 0; mi < 2; ++mi)
#pragma unroll
        for (int ni = 0; ni < 8; ++ni)
#pragma unroll
            for (int r = 0; r < 4; ++r) acc[mi][ni][r] = 0.f;

    for (int it = 0; it < T; ++it) {
        asm volatile("cp.async.wait_group 1;");
        __syncthreads();
        if (it + 2 < T) {
            int s = (it + 2) % STAGES;
            ISSUE_TILE((it + 2) * 32, s);
        }
        const int sb = it % STAGES;
        const uint32_t aBase = smem_base + (uint32_t)(sb * AS_W) * 4 + a_off;
        const uint32_t bBase = smem_base +
            (uint32_t)(STAGES * AS_W + sb * BS_W) * 4 + b_off;

#pragma unroll
        for (int kk = 0; kk < 32; kk += 8) {
            uint32_t af[2][4];
            ldsm4(af[0], aBase + kk * 4);
            ldsm4(af[1], aBase + 16 * 36 * 4 + kk * 4);
            uint32_t bf[4][4];
#pragma unroll
            for (int p = 0; p < 4; ++p)
                ldsm4(bf[p], bBase + p * 16 * 36 * 4 + kk * 4);
#pragma unroll
            for (int ni = 0; ni < 8; ++ni) {
                uint32_t b0 = bf[ni >> 1][(ni & 1) * 2 + 0];
                uint32_t b1 = bf[ni >> 1][(ni & 1) * 2 + 1];
                mma_tf32(acc[0][ni], af[0], b0, b1);
                mma_tf32(acc[1][ni], af[1], b0, b1);
            }
        }
    }
#undef ISSUE_TILE

    // epilogue
    const int base_m = blockIdx.y * 128 + wm0;
    const int base_n = blockIdx.x * 128 + wn0;
#pragma unroll
    for (int mi = 0; mi < 2; ++mi) {
#pragma unroll
        for (int rr = 0; rr < 2; ++rr) {
            int row = base_m + mi * 16 + rr * 8 + group;
#pragma unroll
            for (int ni = 0; ni < 8; ++ni) {
                int col = base_n + ni * 8 + tig * 2;
                float v0 = acc[mi][ni][rr * 2 + 0];
                float v1 = acc[mi][ni][rr * 2 + 1];
                if (HAS_BIAS) { v0 += bias[col]; v1 += bias[col + 1]; }
                if (DO_GELU) {
                    v0 = 0.5f * v0 * (1.0f + erff(v0 * 0.70710678118654752f));
                    v1 = 0.5f * v1 * (1.0f + erff(v1 * 0.70710678118654752f));
                }
                if (OUT_TF32) {
                    uint32_t* p = (uint32_t*)Cv + (size_t)row * N + col;
                    *(uint2*)p = make_uint2(f2tf32(v0), f2tf32(v1));
                } else {
                    float* p = (float*)Cv + (size_t)row * N + col;
                    if (RESID) {
                        float2 r = *(float2*)p;
                        v0 += r.x; v1 += r.y;
                    }
                    *(float2*)p = make_float2(v0, v1);
                }
            }
        }
    }
}

// ---------------- TF32 tensor-core flash attention ----------------------------
// grid: (SEQ/64, NB*HEADS), block 128 (4 warps), each warp owns 16 Q rows.
// Output written as tf32 (feeds O-projection GEMM directly).
#define ATT_STRIDE 68
#define ATT_SMEM_WORDS (3 * 64 * ATT_STRIDE)
#define ATT_SMEM_BYTES (ATT_SMEM_WORDS * 4)

__global__ __launch_bounds__(128, 4) void attention_kernel(
    const float* __restrict__ qkv, uint32_t* __restrict__ out) {
    extern __shared__ uint32_t smem[];
    typedef uint32_t Tile[64][ATT_STRIDE];
    Tile& Ks = *(Tile*)smem;
    Tile& Vs = *(Tile*)(smem + 64 * ATT_STRIDE);
    Tile& Ps = *(Tile*)(smem + 2 * 64 * ATT_STRIDE);  // also used for Q staging

    const int tid  = threadIdx.x;
    const int lane = tid & 31;
    const int w    = tid >> 5;           // warp 0..3
    const int g    = lane >> 2;          // 0..7
    const int t    = lane & 3;           // 0..3

    const int bh = blockIdx.y;
    const int b  = bh / HEADS;
    const int h  = bh % HEADS;
    const int q0 = blockIdx.x * 64;      // CTA's first q row

    const float* qbase = qkv + ((size_t)(b * SEQ + q0)) * (3 * DIM) + h * DH;

    // ---- stage Q (scaled, tf32) into Ps region, then load A-fragments -------
#pragma unroll
    for (int f = 0; f < 8; ++f) {
        int idx = f * 128 + tid;             // 0..1023 float4 ids
        int r = idx >> 4;
        int c = (idx & 15) << 2;
        float4 v = *(const float4*)&qbase[(size_t)r * (3 * DIM) + c];
        *(uint4*)&Ps[r][c] = make_uint4(f2tf32(v.x * 0.125f), f2tf32(v.y * 0.125f),
                                        f2tf32(v.z * 0.125f), f2tf32(v.w * 0.125f));
    }
    __syncthreads();
    uint32_t qa[8][4];
    const int wr = w * 16;
#pragma unroll
    for (int kc = 0; kc < 8; ++kc) {
        qa[kc][0] = Ps[wr + g][kc * 8 + t];
        qa[kc][1] = Ps[wr + g + 8][kc * 8 + t];
        qa[kc][2] = Ps[wr + g][kc * 8 + t + 4];
        qa[kc][3] = Ps[wr + g + 8][kc * 8 + t + 4];
    }

    float m0 = -1e30f, m1 = -1e30f, l0 = 0.f, l1 = 0.f;
    float o[8][4];
#pragma unroll
    for (int ni = 0; ni < 8; ++ni)
#pragma unroll
        for (int r = 0; r < 4; ++r) o[ni][r] = 0.f;

    const float* kbase = qkv + ((size_t)(b * SEQ)) * (3 * DIM) + DIM + h * DH;
    const float* vbase = kbase + DIM;

    for (int jt = 0; jt < SEQ / 64; ++jt) {
        __syncthreads();   // prior iteration done reading Ks/Vs (iter0: Q frags done)
#pragma unroll
        for (int f = 0; f < 8; ++f) {
            int idx = f * 128 + tid;
            int r = idx >> 4;
            int c = (idx & 15) << 2;
            size_t off = (size_t)(jt * 64 + r) * (3 * DIM) + c;
            float4 kv = *(const float4*)&kbase[off];
            float4 vv = *(const float4*)&vbase[off];
            *(uint4*)&Ks[r][c] = make_uint4(f2tf32(kv.x), f2tf32(kv.y),
                                            f2tf32(kv.z), f2tf32(kv.w));
            *(uint4*)&Vs[r][c] = make_uint4(f2tf32(vv.x), f2tf32(vv.y),
                                            f2tf32(vv.z), f2tf32(vv.w));
        }
        __syncthreads();

        // ---- S = Q K^T : warp computes [16 x 64] ----
        float s[8][4];
#pragma unroll
        for (int ni = 0; ni < 8; ++ni)
#pragma unroll
            for (int r = 0; r < 4; ++r) s[ni][r] = 0.f;
#pragma unroll
        for (int kk = 0; kk < 8; ++kk) {
#pragma unroll
            for (int ni = 0; ni < 8; ++ni) {
                uint32_t b0 = Ks[ni * 8 + g][kk * 8 + t];
                uint32_t b1 = Ks[ni * 8 + g][kk * 8 + t + 4];
                mma_tf32(s[ni], qa[kk], b0, b1);
            }
        }

        // ---- online softmax on fragments ----
        float rmax0 = -1e30f, rmax1 = -1e30f;
#pragma unroll
        for (int ni = 0; ni < 8; ++ni) {
            rmax0 = fmaxf(rmax0, fmaxf(s[ni][0], s[ni][1]));
            rmax1 = fmaxf(rmax1, fmaxf(s[ni][2], s[ni][3]));
        }
#pragma unroll
        for (int ofs = 1; ofs <= 2; ofs <<= 1) {
            rmax0 = fmaxf(rmax0, __shfl_xor_sync(0xffffffffu, rmax0, ofs));
            rmax1 = fmaxf(rmax1, __shfl_xor_sync(0xffffffffu, rmax1, ofs));
        }
        float mn0 = fmaxf(m0, rmax0), mn1 = fmaxf(m1, rmax1);
        float corr0 = __expf(m0 - mn0), corr1 = __expf(m1 - mn1);
        m0 = mn0; m1 = mn1;
        float ps0 = 0.f, ps1 = 0.f;
#pragma unroll
        for (int ni = 0; ni < 8; ++ni) {
            float p0 = __expf(s[ni][0] - m0);
            float p1 = __expf(s[ni][1] - m0);
            float p2 = __expf(s[ni][2] - m1);
            float p3 = __expf(s[ni][3] - m1);
            ps0 += p0 + p1; ps1 += p2 + p3;
            // write P (tf32) to smem in accumulator layout
            *(uint2*)&Ps[wr + g][ni * 8 + 2 * t]     = make_uint2(f2tf32(p0), f2tf32(p1));
            *(uint2*)&Ps[wr + g + 8][ni * 8 + 2 * t] = make_uint2(f2tf32(p2), f2tf32(p3));
        }
#pragma unroll
        for (int ofs = 1; ofs <= 2; ofs <<= 1) {
            ps0 += __shfl_xor_sync(0xffffffffu, ps0, ofs);
            ps1 += __shfl_xor_sync(0xffffffffu, ps1, ofs);
        }
        l0 = l0 * corr0 + ps0;
        l1 = l1 * corr1 + ps1;
#pragma unroll
        for (int ni = 0; ni < 8; ++ni) {
            o[ni][0] *= corr0; o[ni][1] *= corr0;
            o[ni][2] *= corr1; o[ni][3] *= corr1;
        }
        __syncwarp();

        // ---- O += P V : warp computes [16 x 64] ----
#pragma unroll
        for (int kk = 0; kk < 8; ++kk) {
            uint32_t pa[4];
            pa[0] = Ps[wr + g][kk * 8 + t];
            pa[1] = Ps[wr + g + 8][kk * 8 + t];
            pa[2] = Ps[wr + g][kk * 8 + t + 4];
            pa[3] = Ps[wr + g + 8][kk * 8 + t + 4];
#pragma unroll
            for (int ni = 0; ni < 8; ++ni) {
                uint32_t b0 = Vs[kk * 8 + t][ni * 8 + g];
                uint32_t b1 = Vs[kk * 8 + t + 4][ni * 8 + g];
                mma_tf32(o[ni], pa, b0, b1);
            }
        }
    }

    // ---- epilogue (tf32 out) ----
    float inv0 = 1.0f / l0, inv1 = 1.0f / l1;
    const int row0 = q0 + wr + g;
    const int row1 = row0 + 8;
    uint32_t* ob0 = out + (size_t)(b * SEQ + row0) * DIM + h * DH;
    uint32_t* ob1 = out + (size_t)(b * SEQ + row1) * DIM + h * DH;
#pragma unroll
    for (int ni = 0; ni < 8; ++ni) {
        int c = ni * 8 + 2 * t;
        *(uint2*)&ob0[c] = make_uint2(f2tf32(o[ni][0] * inv0), f2tf32(o[ni][1] * inv0));
        *(uint2*)&ob1[c] = make_uint2(f2tf32(o[ni][2] * inv1), f2tf32(o[ni][3] * inv1));
    }
}

// ---------------- host side ---------------------------------------------------
extern "C" void kernel_launch(void* const* d_in, const int* in_sizes, int n_in,
                              void* d_out, int out_size) {
    const float* x      = (const float*)d_in[0];
    const float* ln1_w  = (const float*)d_in[1];
    const float* ln1_b  = (const float*)d_in[2];
    const float* w_qkv  = (const float*)d_in[3];
    const float* w_o    = (const float*)d_in[4];
    const float* b_o    = (const float*)d_in[5];
    const float* ln2_w  = (const float*)d_in[6];
    const float* ln2_b  = (const float*)d_in[7];
    const float* w1     = (const float*)d_in[8];
    const float* b1     = (const float*)d_in[9];
    const float* w2     = (const float*)d_in[10];
    const float* b2     = (const float*)d_in[11];

    float* X = (float*)d_out;

    uint32_t *pH, *pATT, *pMLP;
    float* pQKV;
    uint32_t *pWQKV, *pWO, *pW1, *pW2;
    cudaGetSymbolAddress((void**)&pH,    g_h);
    cudaGetSymbolAddress((void**)&pQKV,  g_qkv);
    cudaGetSymbolAddress((void**)&pATT,  g_attn);
    cudaGetSymbolAddress((void**)&pMLP,  g_mlp);
    cudaGetSymbolAddress((void**)&pWQKV, g_wqkv_t);
    cudaGetSymbolAddress((void**)&pWO,   g_wo_t);
    cudaGetSymbolAddress((void**)&pW1,   g_w1_t);
    cudaGetSymbolAddress((void**)&pW2,   g_w2_t);

    // raise dynamic smem limits (idempotent, not a stream op)
    cudaFuncSetAttribute(tf32_gemm_kernel<false, false, false, false>,
                         cudaFuncAttributeMaxDynamicSharedMemorySize, GEMM_SMEM_BYTES);
    cudaFuncSetAttribute(tf32_gemm_kernel<true, true, false, false>,
                         cudaFuncAttributeMaxDynamicSharedMemorySize, GEMM_SMEM_BYTES);
    cudaFuncSetAttribute(tf32_gemm_kernel<true, false, true, true>,
                         cudaFuncAttributeMaxDynamicSharedMemorySize, GEMM_SMEM_BYTES);
    cudaFuncSetAttribute(attention_kernel,
                         cudaFuncAttributeMaxDynamicSharedMemorySize, ATT_SMEM_BYTES);

    // convert + transpose all weights to tf32 [N][K] once
    cvtT_kernel<<<dim3(3 * DIM / 32, DIM / 32, 6), dim3(32, 8)>>>(w_qkv, pWQKV, DIM, 3 * DIM);
    cvtT_kernel<<<dim3(DIM / 32, DIM / 32, 6), dim3(32, 8)>>>(w_o, pWO, DIM, DIM);
    cvtT_kernel<<<dim3(MLPD / 32, DIM / 32, 6), dim3(32, 8)>>>(w1, pW1, DIM, MLPD);
    cvtT_kernel<<<dim3(DIM / 32, MLPD / 32, 6), dim3(32, 8)>>>(w2, pW2, MLPD, DIM);

    cudaMemcpyAsync(X, x, (size_t)TOK * DIM * sizeof(float),
                    cudaMemcpyDeviceToDevice);

    for (int l = 0; l < 6; ++l) {
        const float* l1w = ln1_w + l * DIM;
        const float* l1b = ln1_b + l * DIM;
        const float* bo  = b_o + l * DIM;
        const float* l2w = ln2_w + l * DIM;
        const float* l2b = ln2_b + l * DIM;
        const float* B1  = b1 + l * MLPD;
        const float* B2  = b2 + l * DIM;
        const uint32_t* wqkv = pWQKV + (size_t)l * DIM * 3 * DIM;
        const uint32_t* wo   = pWO   + (size_t)l * DIM * DIM;
        const uint32_t* W1   = pW1   + (size_t)l * DIM * MLPD;
        const uint32_t* W2   = pW2   + (size_t)l * MLPD * DIM;

        // LN1 -> tf32
        layernorm_kernel<<<TOK, 256>>>(X, l1w, l1b, pH);
        // QKV: [4096,768] @ [768,2304] -> fp32
        tf32_gemm_kernel<false, false, false, false>
            <<<dim3(3 * DIM / 128, TOK / 128), 256, GEMM_SMEM_BYTES>>>(
                pH, wqkv, nullptr, pQKV, TOK, 3 * DIM, DIM);
        // fused tensor-core attention -> tf32
        attention_kernel<<<dim3(SEQ / 64, NB * HEADS), 128, ATT_SMEM_BYTES>>>(pQKV, pATT);
        // O-proj + bias + residual into X (fp32)
        tf32_gemm_kernel<true, true, false, false>
            <<<dim3(DIM / 128, TOK / 128), 256, GEMM_SMEM_BYTES>>>(
                pATT, wo, bo, X, TOK, DIM, DIM);
        // LN2 -> tf32
        layernorm_kernel<<<TOK, 256>>>(X, l2w, l2b, pH);
        // MLP1 + bias + exact GELU -> tf32
        tf32_gemm_kernel<true, false, true, true>
            <<<dim3(MLPD / 128, TOK / 128), 256, GEMM_SMEM_BYTES>>>(
                pH, W1, B1, pMLP, TOK, MLPD, DIM);
        // MLP2 + bias + residual into X (fp32)
        tf32_gemm_kernel<true, true, false, false>
            <<<dim3(DIM / 128, TOK / 128), 256, GEMM_SMEM_BYTES>>>(
                pMLP, W2, B2, X, TOK, DIM, MLPD);
    }
}

// round 10
// speedup vs baseline: 3.2559x; 1.4768x over previous
#include <cuda_runtime.h>
#include <cuda_fp16.h>
#include <math.h>
#include <stdint.h>

#define DIM 768
#define MLPD 3072
#define HEADS 12
#define DH 64
#define TOK 4096          // 4 * 1024
#define SEQ 1024
#define NB 4

// ---------------- scratch buffers (device globals; no allocation allowed) ----
__device__ __half   g_h[TOK * DIM];        // LN output (fp16)
__device__ float    g_qkv[TOK * 3 * DIM];  // qkv projections (fp32)
__device__ __half   g_attn[TOK * DIM];     // attention output (fp16)
__device__ __half   g_mlp[TOK * MLPD];     // MLP hidden (fp16)

// fp16 weight copies, TRANSPOSED to [N][K] (converted once per launch)
__device__ __half g_wqkv_t[6 * DIM * 3 * DIM];
__device__ __half g_wo_t[6 * DIM * DIM];
__device__ __half g_w1_t[6 * DIM * MLPD];
__device__ __half g_w2_t[6 * MLPD * DIM];

// single dynamic shared memory symbol, cast per kernel
extern __shared__ char dyn_smem[];

// ---------------- helpers ------------------------------------------------------
__device__ __forceinline__ uint32_t f2tf32(float f) {
    uint32_t u;
    asm("cvt.rna.tf32.f32 %0, %1;" : "=r"(u) : "f"(f));
    return u;
}

__device__ __forceinline__ void mma_tf32(float c[4], const uint32_t a[4],
                                         uint32_t b0, uint32_t b1) {
    asm volatile(
        "mma.sync.aligned.m16n8k8.row.col.f32.tf32.tf32.f32 "
        "{%0,%1,%2,%3}, {%4,%5,%6,%7}, {%8,%9}, {%0,%1,%2,%3};"
        : "+f"(c[0]), "+f"(c[1]), "+f"(c[2]), "+f"(c[3])
        : "r"(a[0]), "r"(a[1]), "r"(a[2]), "r"(a[3]), "r"(b0), "r"(b1));
}

__device__ __forceinline__ void mma_fp16(float c[4], const uint32_t a[4],
                                         uint32_t b0, uint32_t b1) {
    asm volatile(
        "mma.sync.aligned.m16n8k16.row.col.f32.f16.f16.f32 "
        "{%0,%1,%2,%3}, {%4,%5,%6,%7}, {%8,%9}, {%0,%1,%2,%3};"
        : "+f"(c[0]), "+f"(c[1]), "+f"(c[2]), "+f"(c[3])
        : "r"(a[0]), "r"(a[1]), "r"(a[2]), "r"(a[3]), "r"(b0), "r"(b1));
}

__device__ __forceinline__ void ldsm4(uint32_t r[4], uint32_t saddr) {
    asm volatile("ldmatrix.sync.aligned.m8n8.x4.shared.b16 {%0,%1,%2,%3}, [%4];"
                 : "=r"(r[0]), "=r"(r[1]), "=r"(r[2]), "=r"(r[3])
                 : "r"(saddr));
}

__device__ __forceinline__ void cp_async16(uint32_t saddr, const void* gptr) {
    asm volatile("cp.async.cg.shared.global [%0], [%1], 16;"
                 :: "r"(saddr), "l"(gptr));
}
__device__ __forceinline__ void cp_commit() {
    asm volatile("cp.async.commit_group;");
}

// ---------------- fp32 [K,N] -> fp16 [N,K] transpose-convert -----------------
// block (32,8); grid (N/32, K/32, layers)
__global__ void cvtT_kernel(const float* __restrict__ in,
                            __half* __restrict__ out, int K, int N) {
    __shared__ __half tile[32][34];
    const size_t lofs = (size_t)blockIdx.z * K * N;
    const float* inL = in + lofs;
    __half* outL = out + lofs;
    int k0 = blockIdx.y * 32, n0 = blockIdx.x * 32;
#pragma unroll
    for (int i = threadIdx.y; i < 32; i += 8)
        tile[i][threadIdx.x] =
            __float2half_rn(inL[(size_t)(k0 + i) * N + n0 + threadIdx.x]);
    __syncthreads();
#pragma unroll
    for (int i = threadIdx.y; i < 32; i += 8)
        outL[(size_t)(n0 + i) * K + k0 + threadIdx.x] = tile[threadIdx.x][i];
}

// ---------------- LayerNorm: one block per row, writes fp16 -------------------
__global__ void layernorm_kernel(const float* __restrict__ x,
                                 const float* __restrict__ w,
                                 const float* __restrict__ b,
                                 __half* __restrict__ out) {
    int row = blockIdx.x;
    const float* xr = x + (size_t)row * DIM;
    float vals[3];
    float s = 0.f, ss = 0.f;
#pragma unroll
    for (int i = 0; i < 3; ++i) {
        float v = xr[threadIdx.x + 256 * i];
        vals[i] = v;
        s += v;
        ss += v * v;
    }
#pragma unroll
    for (int o = 16; o; o >>= 1) {
        s  += __shfl_xor_sync(0xffffffffu, s, o);
        ss += __shfl_xor_sync(0xffffffffu, ss, o);
    }
    __shared__ float shs[8], shss[8];
    __shared__ float mean_s, rstd_s;
    int wid = threadIdx.x >> 5, lid = threadIdx.x & 31;
    if (lid == 0) { shs[wid] = s; shss[wid] = ss; }
    __syncthreads();
    if (threadIdx.x == 0) {
        float S = 0.f, SS = 0.f;
#pragma unroll
        for (int i = 0; i < 8; ++i) { S += shs[i]; SS += shss[i]; }
        float mean = S * (1.0f / DIM);
        float var  = SS * (1.0f / DIM) - mean * mean;
        mean_s = mean;
        rstd_s = rsqrtf(var + 1e-5f);
    }
    __syncthreads();
    float mean = mean_s, rstd = rstd_s;
    __half* orow = out + (size_t)row * DIM;
#pragma unroll
    for (int i = 0; i < 3; ++i) {
        int idx = threadIdx.x + 256 * i;
        orow[idx] = __float2half_rn((vals[i] - mean) * rstd * w[idx] + b[idx]);
    }
}

// ---------------- FP16 tensor-core GEMM, 3-stage cp.async + ldmatrix ----------
// C[M,N] = op( A[M,K] @ B^T + bias ) (+ residual), A [M][K] fp16, B [N][K] fp16.
// block tile 128x128, K-tile 64 (=128B rows), 8 warps (4x2), warp tile 32x64,
// fp16 m16n8k16 MMA with fp32 accumulators.
#define GSTAGES 3
#define RSB 144                     // smem row stride bytes (36 words: banks 4r)
#define A_STG (128 * RSB)           // 18432 B
#define B_STG (128 * RSB)
#define SM_A 0
#define SM_B (GSTAGES * A_STG)
#define GEMM_SMEM_BYTES (GSTAGES * (A_STG + B_STG))   // 110592

template <bool HAS_BIAS, bool RESID, bool DO_GELU, bool OUT_HALF>
__global__ __launch_bounds__(256, 2) void fp16_gemm_kernel(
    const __half* __restrict__ A, const __half* __restrict__ B,
    const float* __restrict__ bias, void* __restrict__ Cv,
    int M, int N, int K) {
    const uint32_t sbase = (uint32_t)__cvta_generic_to_shared(dyn_smem);

    const int tid   = threadIdx.x;
    const int lane  = tid & 31;
    const int wid   = tid >> 5;
    const int group = lane >> 2;   // 0..7
    const int tig   = lane & 3;    // 0..3
    const int wm0   = (wid >> 1) * 32;  // warp row offset 0..96
    const int wn0   = (wid & 1) * 64;   // warp col offset 0/64

    const __half* Ab = A + (size_t)(blockIdx.y * 128) * K;
    const __half* Bb = B + (size_t)(blockIdx.x * 128) * K;  // [N][K]

    // ldmatrix per-lane byte offsets within a stage buffer
    // A frag (m16k16): lanes 0-7 rows m..m+7 klo, 8-15 rows +8 klo,
    //                  16-23 rows m..m+7 khi(+16B), 24-31 rows +8 khi
    const uint32_t a_off =
        (uint32_t)(wm0 + (lane & 7) + (((lane >> 3) & 1) * 8)) * RSB +
        (uint32_t)((lane >> 4) & 1) * 16;
    // B frags (two n8k16 blocks per ldsm4): lanes 0-7 n..n+7 klo, 8-15 khi,
    //                                       16-23 n+8 klo, 24-31 n+8 khi
    const uint32_t b_off =
        (uint32_t)(wn0 + (lane & 7) + (((lane >> 4) & 1) * 8)) * RSB +
        (uint32_t)((lane >> 3) & 1) * 16;

    const int T = K / 64;

#define ISSUE_TILE(kt, s)                                                     \
    do {                                                                      \
        uint32_t abase_ = sbase + SM_A + (s) * A_STG;                         \
        uint32_t bbase_ = sbase + SM_B + (s) * B_STG;                         \
        _Pragma("unroll")                                                     \
        for (int i_ = 0; i_ < 4; ++i_) {                                      \
            int c_ = tid + i_ * 256;                                          \
            int row_ = c_ >> 3, col_ = c_ & 7;                                \
            cp_async16(abase_ + row_ * RSB + col_ * 16,                       \
                       Ab + (size_t)row_ * K + (kt) + col_ * 8);              \
            cp_async16(bbase_ + row_ * RSB + col_ * 16,                       \
                       Bb + (size_t)row_ * K + (kt) + col_ * 8);              \
        }                                                                     \
        cp_commit();                                                          \
    } while (0)

    ISSUE_TILE(0, 0);
    ISSUE_TILE(64, 1);

    float acc[2][8][4];
#pragma unroll
    for (int mi = 0; mi < 2; ++mi)
#pragma unroll
        for (int ni = 0; ni < 8; ++ni)
#pragma unroll
            for (int r = 0; r < 4; ++r) acc[mi][ni][r] = 0.f;

    for (int it = 0; it < T; ++it) {
        asm volatile("cp.async.wait_group 1;" ::: "memory");
        __syncthreads();
        if (it + 2 < T) ISSUE_TILE((it + 2) * 64, (it + 2) % GSTAGES);

        const int sb = it % GSTAGES;
        const uint32_t aBase = sbase + SM_A + sb * A_STG + a_off;
        const uint32_t bBase = sbase + SM_B + sb * B_STG + b_off;

#pragma unroll
        for (int kk = 0; kk < 4; ++kk) {     // 4 k16-steps cover K-tile 64
            uint32_t af[2][4];
            ldsm4(af[0], aBase + kk * 32);
            ldsm4(af[1], aBase + 16 * RSB + kk * 32);
            uint32_t bf[4][4];
#pragma unroll
            for (int p = 0; p < 4; ++p)
                ldsm4(bf[p], bBase + p * 16 * RSB + kk * 32);
#pragma unroll
            for (int ni = 0; ni < 8; ++ni) {
                uint32_t b0 = bf[ni >> 1][(ni & 1) * 2 + 0];
                uint32_t b1 = bf[ni >> 1][(ni & 1) * 2 + 1];
                mma_fp16(acc[0][ni], af[0], b0, b1);
                mma_fp16(acc[1][ni], af[1], b0, b1);
            }
        }
    }
#undef ISSUE_TILE

    // epilogue
    const int base_m = blockIdx.y * 128 + wm0;
    const int base_n = blockIdx.x * 128 + wn0;
#pragma unroll
    for (int mi = 0; mi < 2; ++mi) {
#pragma unroll
        for (int rr = 0; rr < 2; ++rr) {
            int row = base_m + mi * 16 + rr * 8 + group;
#pragma unroll
            for (int ni = 0; ni < 8; ++ni) {
                int col = base_n + ni * 8 + tig * 2;
                float v0 = acc[mi][ni][rr * 2 + 0];
                float v1 = acc[mi][ni][rr * 2 + 1];
                if (HAS_BIAS) { v0 += bias[col]; v1 += bias[col + 1]; }
                if (DO_GELU) {
                    v0 = 0.5f * v0 * (1.0f + erff(v0 * 0.70710678118654752f));
                    v1 = 0.5f * v1 * (1.0f + erff(v1 * 0.70710678118654752f));
                }
                if (OUT_HALF) {
                    __half2* p = (__half2*)((__half*)Cv + (size_t)row * N + col);
                    *p = __float22half2_rn(make_float2(v0, v1));
                } else {
                    float* p = (float*)Cv + (size_t)row * N + col;
                    if (RESID) {
                        float2 r = *(float2*)p;
                        v0 += r.x; v1 += r.y;
                    }
                    *(float2*)p = make_float2(v0, v1);
                }
            }
        }
    }
}

// ---------------- TF32 tensor-core flash attention (mma.sync) -----------------
// grid: (SEQ/64, NB*HEADS), block 128 (4 warps). Output written as fp16.
#define ATT_STRIDE 68
#define ATT_SMEM_WORDS (3 * 64 * ATT_STRIDE)
#define ATT_SMEM_BYTES (ATT_SMEM_WORDS * 4)

__global__ __launch_bounds__(128, 4) void attention_kernel(
    const float* __restrict__ qkv, __half* __restrict__ out) {
    uint32_t* smem = (uint32_t*)dyn_smem;
    typedef uint32_t Tile[64][ATT_STRIDE];
    Tile& Ks = *(Tile*)smem;
    Tile& Vs = *(Tile*)(smem + 64 * ATT_STRIDE);
    Tile& Ps = *(Tile*)(smem + 2 * 64 * ATT_STRIDE);

    const int tid  = threadIdx.x;
    const int lane = tid & 31;
    const int w    = tid >> 5;
    const int g    = lane >> 2;
    const int t    = lane & 3;

    const int bh = blockIdx.y;
    const int b  = bh / HEADS;
    const int h  = bh % HEADS;
    const int q0 = blockIdx.x * 64;

    const float* qbase = qkv + ((size_t)(b * SEQ + q0)) * (3 * DIM) + h * DH;

#pragma unroll
    for (int f = 0; f < 8; ++f) {
        int idx = f * 128 + tid;
        int r = idx >> 4;
        int c = (idx & 15) << 2;
        float4 v = *(const float4*)&qbase[(size_t)r * (3 * DIM) + c];
        *(uint4*)&Ps[r][c] = make_uint4(f2tf32(v.x * 0.125f), f2tf32(v.y * 0.125f),
                                        f2tf32(v.z * 0.125f), f2tf32(v.w * 0.125f));
    }
    __syncthreads();
    uint32_t qa[8][4];
    const int wr = w * 16;
#pragma unroll
    for (int kc = 0; kc < 8; ++kc) {
        qa[kc][0] = Ps[wr + g][kc * 8 + t];
        qa[kc][1] = Ps[wr + g + 8][kc * 8 + t];
        qa[kc][2] = Ps[wr + g][kc * 8 + t + 4];
        qa[kc][3] = Ps[wr + g + 8][kc * 8 + t + 4];
    }

    float m0 = -1e30f, m1 = -1e30f, l0 = 0.f, l1 = 0.f;
    float o[8][4];
#pragma unroll
    for (int ni = 0; ni < 8; ++ni)
#pragma unroll
        for (int r = 0; r < 4; ++r) o[ni][r] = 0.f;

    const float* kbase = qkv + ((size_t)(b * SEQ)) * (3 * DIM) + DIM + h * DH;
    const float* vbase = kbase + DIM;

    for (int jt = 0; jt < SEQ / 64; ++jt) {
        __syncthreads();
#pragma unroll
        for (int f = 0; f < 8; ++f) {
            int idx = f * 128 + tid;
            int r = idx >> 4;
            int c = (idx & 15) << 2;
            size_t off = (size_t)(jt * 64 + r) * (3 * DIM) + c;
            float4 kv = *(const float4*)&kbase[off];
            float4 vv = *(const float4*)&vbase[off];
            *(uint4*)&Ks[r][c] = make_uint4(f2tf32(kv.x), f2tf32(kv.y),
                                            f2tf32(kv.z), f2tf32(kv.w));
            *(uint4*)&Vs[r][c] = make_uint4(f2tf32(vv.x), f2tf32(vv.y),
                                            f2tf32(vv.z), f2tf32(vv.w));
        }
        __syncthreads();

        float s[8][4];
#pragma unroll
        for (int ni = 0; ni < 8; ++ni)
#pragma unroll
            for (int r = 0; r < 4; ++r) s[ni][r] = 0.f;
#pragma unroll
        for (int kk = 0; kk < 8; ++kk) {
#pragma unroll
            for (int ni = 0; ni < 8; ++ni) {
                uint32_t b0 = Ks[ni * 8 + g][kk * 8 + t];
                uint32_t b1 = Ks[ni * 8 + g][kk * 8 + t + 4];
                mma_tf32(s[ni], qa[kk], b0, b1);
            }
        }

        float rmax0 = -1e30f, rmax1 = -1e30f;
#pragma unroll
        for (int ni = 0; ni < 8; ++ni) {
            rmax0 = fmaxf(rmax0, fmaxf(s[ni][0], s[ni][1]));
            rmax1 = fmaxf(rmax1, fmaxf(s[ni][2], s[ni][3]));
        }
#pragma unroll
        for (int ofs = 1; ofs <= 2; ofs <<= 1) {
            rmax0 = fmaxf(rmax0, __shfl_xor_sync(0xffffffffu, rmax0, ofs));
            rmax1 = fmaxf(rmax1, __shfl_xor_sync(0xffffffffu, rmax1, ofs));
        }
        float mn0 = fmaxf(m0, rmax0), mn1 = fmaxf(m1, rmax1);
        float corr0 = __expf(m0 - mn0), corr1 = __expf(m1 - mn1);
        m0 = mn0; m1 = mn1;
        float ps0 = 0.f, ps1 = 0.f;
#pragma unroll
        for (int ni = 0; ni < 8; ++ni) {
            float p0 = __expf(s[ni][0] - m0);
            float p1 = __expf(s[ni][1] - m0);
            float p2 = __expf(s[ni][2] - m1);
            float p3 = __expf(s[ni][3] - m1);
            ps0 += p0 + p1; ps1 += p2 + p3;
            *(uint2*)&Ps[wr + g][ni * 8 + 2 * t]     = make_uint2(f2tf32(p0), f2tf32(p1));
            *(uint2*)&Ps[wr + g + 8][ni * 8 + 2 * t] = make_uint2(f2tf32(p2), f2tf32(p3));
        }
#pragma unroll
        for (int ofs = 1; ofs <= 2; ofs <<= 1) {
            ps0 += __shfl_xor_sync(0xffffffffu, ps0, ofs);
            ps1 += __shfl_xor_sync(0xffffffffu, ps1, ofs);
        }
        l0 = l0 * corr0 + ps0;
        l1 = l1 * corr1 + ps1;
#pragma unroll
        for (int ni = 0; ni < 8; ++ni) {
            o[ni][0] *= corr0; o[ni][1] *= corr0;
            o[ni][2] *= corr1; o[ni][3] *= corr1;
        }
        __syncwarp();

#pragma unroll
        for (int kk = 0; kk < 8; ++kk) {
            uint32_t pa[4];
            pa[0] = Ps[wr + g][kk * 8 + t];
            pa[1] = Ps[wr + g + 8][kk * 8 + t];
            pa[2] = Ps[wr + g][kk * 8 + t + 4];
            pa[3] = Ps[wr + g + 8][kk * 8 + t + 4];
#pragma unroll
            for (int ni = 0; ni < 8; ++ni) {
                uint32_t b0 = Vs[kk * 8 + t][ni * 8 + g];
                uint32_t b1 = Vs[kk * 8 + t + 4][ni * 8 + g];
                mma_tf32(o[ni], pa, b0, b1);
            }
        }
    }

    float inv0 = 1.0f / l0, inv1 = 1.0f / l1;
    const int row0 = q0 + wr + g;
    const int row1 = row0 + 8;
    __half* ob0 = out + (size_t)(b * SEQ + row0) * DIM + h * DH;
    __half* ob1 = out + (size_t)(b * SEQ + row1) * DIM + h * DH;
#pragma unroll
    for (int ni = 0; ni < 8; ++ni) {
        int c = ni * 8 + 2 * t;
        *(__half2*)&ob0[c] = __float22half2_rn(make_float2(o[ni][0] * inv0, o[ni][1] * inv0));
        *(__half2*)&ob1[c] = __float22half2_rn(make_float2(o[ni][2] * inv1, o[ni][3] * inv1));
    }
}

// ---------------- host side ---------------------------------------------------
extern "C" void kernel_launch(void* const* d_in, const int* in_sizes, int n_in,
                              void* d_out, int out_size) {
    const float* x      = (const float*)d_in[0];
    const float* ln1_w  = (const float*)d_in[1];
    const float* ln1_b  = (const float*)d_in[2];
    const float* w_qkv  = (const float*)d_in[3];
    const float* w_o    = (const float*)d_in[4];
    const float* b_o    = (const float*)d_in[5];
    const float* ln2_w  = (const float*)d_in[6];
    const float* ln2_b  = (const float*)d_in[7];
    const float* w1     = (const float*)d_in[8];
    const float* b1     = (const float*)d_in[9];
    const float* w2     = (const float*)d_in[10];
    const float* b2     = (const float*)d_in[11];

    float* X = (float*)d_out;

    __half *pH, *pATT, *pMLP;
    float* pQKV;
    __half *pWQKV, *pWO, *pW1, *pW2;
    cudaGetSymbolAddress((void**)&pH,    g_h);
    cudaGetSymbolAddress((void**)&pQKV,  g_qkv);
    cudaGetSymbolAddress((void**)&pATT,  g_attn);
    cudaGetSymbolAddress((void**)&pMLP,  g_mlp);
    cudaGetSymbolAddress((void**)&pWQKV, g_wqkv_t);
    cudaGetSymbolAddress((void**)&pWO,   g_wo_t);
    cudaGetSymbolAddress((void**)&pW1,   g_w1_t);
    cudaGetSymbolAddress((void**)&pW2,   g_w2_t);

    cudaFuncSetAttribute(fp16_gemm_kernel<false, false, false, false>,
                         cudaFuncAttributeMaxDynamicSharedMemorySize, GEMM_SMEM_BYTES);
    cudaFuncSetAttribute(fp16_gemm_kernel<true, true, false, false>,
                         cudaFuncAttributeMaxDynamicSharedMemorySize, GEMM_SMEM_BYTES);
    cudaFuncSetAttribute(fp16_gemm_kernel<true, false, true, true>,
                         cudaFuncAttributeMaxDynamicSharedMemorySize, GEMM_SMEM_BYTES);
    cudaFuncSetAttribute(attention_kernel,
                         cudaFuncAttributeMaxDynamicSharedMemorySize, ATT_SMEM_BYTES);

    // convert + transpose all weights to fp16 [N][K] once
    cvtT_kernel<<<dim3(3 * DIM / 32, DIM / 32, 6), dim3(32, 8)>>>(w_qkv, pWQKV, DIM, 3 * DIM);
    cvtT_kernel<<<dim3(DIM / 32, DIM / 32, 6), dim3(32, 8)>>>(w_o, pWO, DIM, DIM);
    cvtT_kernel<<<dim3(MLPD / 32, DIM / 32, 6), dim3(32, 8)>>>(w1, pW1, DIM, MLPD);
    cvtT_kernel<<<dim3(DIM / 32, MLPD / 32, 6), dim3(32, 8)>>>(w2, pW2, MLPD, DIM);

    cudaMemcpyAsync(X, x, (size_t)TOK * DIM * sizeof(float),
                    cudaMemcpyDeviceToDevice);

    for (int l = 0; l < 6; ++l) {
        const float* l1w = ln1_w + l * DIM;
        const float* l1b = ln1_b + l * DIM;
        const float* bo  = b_o + l * DIM;
        const float* l2w = ln2_w + l * DIM;
        const float* l2b = ln2_b + l * DIM;
        const float* B1  = b1 + l * MLPD;
        const float* B2  = b2 + l * DIM;
        const __half* wqkv = pWQKV + (size_t)l * DIM * 3 * DIM;
        const __half* wo   = pWO   + (size_t)l * DIM * DIM;
        const __half* W1   = pW1   + (size_t)l * DIM * MLPD;
        const __half* W2   = pW2   + (size_t)l * MLPD * DIM;

        // LN1 -> fp16
        layernorm_kernel<<<TOK, 256>>>(X, l1w, l1b, pH);
        // QKV: [4096,768] @ [768,2304] -> fp32
        fp16_gemm_kernel<false, false, false, false>
            <<<dim3(3 * DIM / 128, TOK / 128), 256, GEMM_SMEM_BYTES>>>(
                pH, wqkv, nullptr, pQKV, TOK, 3 * DIM, DIM);
        // fused tensor-core attention -> fp16
        attention_kernel<<<dim3(SEQ / 64, NB * HEADS), 128, ATT_SMEM_BYTES>>>(pQKV, pATT);
        // O-proj + bias + residual into X (fp32)
        fp16_gemm_kernel<true, true, false, false>
            <<<dim3(DIM / 128, TOK / 128), 256, GEMM_SMEM_BYTES>>>(
                pATT, wo, bo, X, TOK, DIM, DIM);
        // LN2 -> fp16
        layernorm_kernel<<<TOK, 256>>>(X, l2w, l2b, pH);
        // MLP1 + bias + exact GELU -> fp16
        fp16_gemm_kernel<true, false, true, true>
            <<<dim3(MLPD / 128, TOK / 128), 256, GEMM_SMEM_BYTES>>>(
                pH, W1, B1, pMLP, TOK, MLPD, DIM);
        // MLP2 + bias + residual into X (fp32)
        fp16_gemm_kernel<true, true, false, false>
            <<<dim3(DIM / 128, TOK / 128), 256, GEMM_SMEM_BYTES>>>(
                pMLP, W2, B2, X, TOK, DIM, MLPD);
    }
}

// round 11
// speedup vs baseline: 4.1266x; 1.2674x over previous
#include <cuda_runtime.h>
#include <cuda_fp16.h>
#include <math.h>
#include <stdint.h>

#define DIM 768
#define MLPD 3072
#define HEADS 12
#define DH 64
#define TOK 4096          // 4 * 1024
#define SEQ 1024
#define NB 4

// ---------------- scratch buffers (device globals; no allocation allowed) ----
__device__ __half   g_h[TOK * DIM];        // LN output (fp16)
__device__ __half   g_qkv[TOK * 3 * DIM];  // qkv projections (fp16)
__device__ __half   g_attn[TOK * DIM];     // attention output (fp16)
__device__ __half   g_mlp[TOK * MLPD];     // MLP hidden (fp16)

// fp16 weight copies, TRANSPOSED to [N][K] (converted once per launch)
__device__ __half g_wqkv_t[6 * DIM * 3 * DIM];
__device__ __half g_wo_t[6 * DIM * DIM];
__device__ __half g_w1_t[6 * DIM * MLPD];
__device__ __half g_w2_t[6 * MLPD * DIM];

// single dynamic shared memory symbol, cast per kernel
extern __shared__ char dyn_smem[];

// ---------------- helpers ------------------------------------------------------
__device__ __forceinline__ void mma_fp16(float c[4], const uint32_t a[4],
                                         uint32_t b0, uint32_t b1) {
    asm volatile(
        "mma.sync.aligned.m16n8k16.row.col.f32.f16.f16.f32 "
        "{%0,%1,%2,%3}, {%4,%5,%6,%7}, {%8,%9}, {%0,%1,%2,%3};"
        : "+f"(c[0]), "+f"(c[1]), "+f"(c[2]), "+f"(c[3])
        : "r"(a[0]), "r"(a[1]), "r"(a[2]), "r"(a[3]), "r"(b0), "r"(b1));
}

__device__ __forceinline__ void ldsm4(uint32_t r[4], uint32_t saddr) {
    asm volatile("ldmatrix.sync.aligned.m8n8.x4.shared.b16 {%0,%1,%2,%3}, [%4];"
                 : "=r"(r[0]), "=r"(r[1]), "=r"(r[2]), "=r"(r[3])
                 : "r"(saddr));
}

__device__ __forceinline__ void ldsm4t(uint32_t r[4], uint32_t saddr) {
    asm volatile("ldmatrix.sync.aligned.m8n8.x4.trans.shared.b16 {%0,%1,%2,%3}, [%4];"
                 : "=r"(r[0]), "=r"(r[1]), "=r"(r[2]), "=r"(r[3])
                 : "r"(saddr));
}

__device__ __forceinline__ void cp_async16(uint32_t saddr, const void* gptr) {
    asm volatile("cp.async.cg.shared.global [%0], [%1], 16;"
                 :: "r"(saddr), "l"(gptr));
}
__device__ __forceinline__ void cp_commit() {
    asm volatile("cp.async.commit_group;");
}

__device__ __forceinline__ uint32_t packh2(float a, float b) {
    __half2 h = __float22half2_rn(make_float2(a, b));
    return *(uint32_t*)&h;
}

// ---------------- fp32 [K,N] -> fp16 [N,K] transpose-convert -----------------
// block (32,8); grid (N/32, K/32, layers)
__global__ void cvtT_kernel(const float* __restrict__ in,
                            __half* __restrict__ out, int K, int N) {
    __shared__ __half tile[32][34];
    const size_t lofs = (size_t)blockIdx.z * K * N;
    const float* inL = in + lofs;
    __half* outL = out + lofs;
    int k0 = blockIdx.y * 32, n0 = blockIdx.x * 32;
#pragma unroll
    for (int i = threadIdx.y; i < 32; i += 8)
        tile[i][threadIdx.x] =
            __float2half_rn(inL[(size_t)(k0 + i) * N + n0 + threadIdx.x]);
    __syncthreads();
#pragma unroll
    for (int i = threadIdx.y; i < 32; i += 8)
        outL[(size_t)(n0 + i) * K + k0 + threadIdx.x] = tile[threadIdx.x][i];
}

// ---------------- LayerNorm: one block per row, writes fp16 -------------------
__global__ void layernorm_kernel(const float* __restrict__ x,
                                 const float* __restrict__ w,
                                 const float* __restrict__ b,
                                 __half* __restrict__ out) {
    int row = blockIdx.x;
    const float* xr = x + (size_t)row * DIM;
    float vals[3];
    float s = 0.f, ss = 0.f;
#pragma unroll
    for (int i = 0; i < 3; ++i) {
        float v = xr[threadIdx.x + 256 * i];
        vals[i] = v;
        s += v;
        ss += v * v;
    }
#pragma unroll
    for (int o = 16; o; o >>= 1) {
        s  += __shfl_xor_sync(0xffffffffu, s, o);
        ss += __shfl_xor_sync(0xffffffffu, ss, o);
    }
    __shared__ float shs[8], shss[8];
    __shared__ float mean_s, rstd_s;
    int wid = threadIdx.x >> 5, lid = threadIdx.x & 31;
    if (lid == 0) { shs[wid] = s; shss[wid] = ss; }
    __syncthreads();
    if (threadIdx.x == 0) {
        float S = 0.f, SS = 0.f;
#pragma unroll
        for (int i = 0; i < 8; ++i) { S += shs[i]; SS += shss[i]; }
        float mean = S * (1.0f / DIM);
        float var  = SS * (1.0f / DIM) - mean * mean;
        mean_s = mean;
        rstd_s = rsqrtf(var + 1e-5f);
    }
    __syncthreads();
    float mean = mean_s, rstd = rstd_s;
    __half* orow = out + (size_t)row * DIM;
#pragma unroll
    for (int i = 0; i < 3; ++i) {
        int idx = threadIdx.x + 256 * i;
        orow[idx] = __float2half_rn((vals[i] - mean) * rstd * w[idx] + b[idx]);
    }
}

// ---------------- FP16 tensor-core GEMM, 3-stage cp.async + ldmatrix ----------
// C[M,N] = op( A[M,K] @ B^T + bias ) (+ residual), A [M][K] fp16, B [N][K] fp16.
// block tile 128x128, K-tile 64 (=128B rows), 8 warps (4x2), warp tile 32x64,
// fp16 m16n8k16 MMA with fp32 accumulators.
#define GSTAGES 3
#define RSB 144                     // smem row stride bytes (36 words)
#define A_STG (128 * RSB)           // 18432 B
#define B_STG (128 * RSB)
#define SM_A 0
#define SM_B (GSTAGES * A_STG)
#define GEMM_SMEM_BYTES (GSTAGES * (A_STG + B_STG))   // 110592

template <bool HAS_BIAS, bool RESID, bool DO_GELU, bool OUT_HALF>
__global__ __launch_bounds__(256, 2) void fp16_gemm_kernel(
    const __half* __restrict__ A, const __half* __restrict__ B,
    const float* __restrict__ bias, void* __restrict__ Cv,
    int M, int N, int K) {
    const uint32_t sbase = (uint32_t)__cvta_generic_to_shared(dyn_smem);

    const int tid   = threadIdx.x;
    const int lane  = tid & 31;
    const int wid   = tid >> 5;
    const int group = lane >> 2;   // 0..7
    const int tig   = lane & 3;    // 0..3
    const int wm0   = (wid >> 1) * 32;  // warp row offset 0..96
    const int wn0   = (wid & 1) * 64;   // warp col offset 0/64

    const __half* Ab = A + (size_t)(blockIdx.y * 128) * K;
    const __half* Bb = B + (size_t)(blockIdx.x * 128) * K;  // [N][K]

    const uint32_t a_off =
        (uint32_t)(wm0 + (lane & 7) + (((lane >> 3) & 1) * 8)) * RSB +
        (uint32_t)((lane >> 4) & 1) * 16;
    const uint32_t b_off =
        (uint32_t)(wn0 + (lane & 7) + (((lane >> 4) & 1) * 8)) * RSB +
        (uint32_t)((lane >> 3) & 1) * 16;

    const int T = K / 64;

#define ISSUE_TILE(kt, s)                                                     \
    do {                                                                      \
        uint32_t abase_ = sbase + SM_A + (s) * A_STG;                         \
        uint32_t bbase_ = sbase + SM_B + (s) * B_STG;                         \
        _Pragma("unroll")                                                     \
        for (int i_ = 0; i_ < 4; ++i_) {                                      \
            int c_ = tid + i_ * 256;                                          \
            int row_ = c_ >> 3, col_ = c_ & 7;                                \
            cp_async16(abase_ + row_ * RSB + col_ * 16,                       \
                       Ab + (size_t)row_ * K + (kt) + col_ * 8);              \
            cp_async16(bbase_ + row_ * RSB + col_ * 16,                       \
                       Bb + (size_t)row_ * K + (kt) + col_ * 8);              \
        }                                                                     \
        cp_commit();                                                          \
    } while (0)

    ISSUE_TILE(0, 0);
    ISSUE_TILE(64, 1);

    float acc[2][8][4];
#pragma unroll
    for (int mi = 0; mi < 2; ++mi)
#pragma unroll
        for (int ni = 0; ni < 8; ++ni)
#pragma unroll
            for (int r = 0; r < 4; ++r) acc[mi][ni][r] = 0.f;

    for (int it = 0; it < T; ++it) {
        asm volatile("cp.async.wait_group 1;" ::: "memory");
        __syncthreads();
        if (it + 2 < T) ISSUE_TILE((it + 2) * 64, (it + 2) % GSTAGES);

        const int sb = it % GSTAGES;
        const uint32_t aBase = sbase + SM_A + sb * A_STG + a_off;
        const uint32_t bBase = sbase + SM_B + sb * B_STG + b_off;

#pragma unroll
        for (int kk = 0; kk < 4; ++kk) {     // 4 k16-steps cover K-tile 64
            uint32_t af[2][4];
            ldsm4(af[0], aBase + kk * 32);
            ldsm4(af[1], aBase + 16 * RSB + kk * 32);
            uint32_t bf[4][4];
#pragma unroll
            for (int p = 0; p < 4; ++p)
                ldsm4(bf[p], bBase + p * 16 * RSB + kk * 32);
#pragma unroll
            for (int ni = 0; ni < 8; ++ni) {
                uint32_t b0 = bf[ni >> 1][(ni & 1) * 2 + 0];
                uint32_t b1 = bf[ni >> 1][(ni & 1) * 2 + 1];
                mma_fp16(acc[0][ni], af[0], b0, b1);
                mma_fp16(acc[1][ni], af[1], b0, b1);
            }
        }
    }
#undef ISSUE_TILE

    // epilogue
    const int base_m = blockIdx.y * 128 + wm0;
    const int base_n = blockIdx.x * 128 + wn0;
#pragma unroll
    for (int mi = 0; mi < 2; ++mi) {
#pragma unroll
        for (int rr = 0; rr < 2; ++rr) {
            int row = base_m + mi * 16 + rr * 8 + group;
#pragma unroll
            for (int ni = 0; ni < 8; ++ni) {
                int col = base_n + ni * 8 + tig * 2;
                float v0 = acc[mi][ni][rr * 2 + 0];
                float v1 = acc[mi][ni][rr * 2 + 1];
                if (HAS_BIAS) { v0 += bias[col]; v1 += bias[col + 1]; }
                if (DO_GELU) {
                    v0 = 0.5f * v0 * (1.0f + erff(v0 * 0.70710678118654752f));
                    v1 = 0.5f * v1 * (1.0f + erff(v1 * 0.70710678118654752f));
                }
                if (OUT_HALF) {
                    __half2* p = (__half2*)((__half*)Cv + (size_t)row * N + col);
                    *p = __float22half2_rn(make_float2(v0, v1));
                } else {
                    float* p = (float*)Cv + (size_t)row * N + col;
                    if (RESID) {
                        float2 r = *(float2*)p;
                        v0 += r.x; v1 += r.y;
                    }
                    *(float2*)p = make_float2(v0, v1);
                }
            }
        }
    }
}

// ---------------- FP16 tensor-core flash attention ----------------------------
// grid: (SEQ/64, NB*HEADS), block 128 (4 warps), each warp owns 16 Q rows.
// QKV input fp16; K via ldmatrix, V via ldmatrix.trans; P never leaves regs.
#define ARS 144                       // row stride bytes (64 halves + 8 pad)
#define AQ 0
#define AK (64 * ARS)
#define AV (2 * 64 * ARS)
#define ATT_SMEM_BYTES (3 * 64 * ARS)  // 27648

__global__ __launch_bounds__(128, 4) void attention_kernel(
    const __half* __restrict__ qkv, __half* __restrict__ out) {
    const uint32_t sbase = (uint32_t)__cvta_generic_to_shared(dyn_smem);
    const int tid  = threadIdx.x;
    const int lane = tid & 31;
    const int w    = tid >> 5;
    const int g    = lane >> 2;
    const int t    = lane & 3;
    const int wr   = w * 16;

    const int bh = blockIdx.y;
    const int b  = bh / HEADS;
    const int h  = bh % HEADS;
    const int q0 = blockIdx.x * 64;

    // ---- stage Q tile (fp16), load A-fragments once --------------------------
    const __half* qbase = qkv + ((size_t)(b * SEQ + q0)) * (3 * DIM) + h * DH;
#pragma unroll
    for (int i = 0; i < 4; ++i) {
        int c = tid + i * 128;
        int row = c >> 3, ch = c & 7;
        cp_async16(sbase + AQ + row * ARS + ch * 16,
                   qbase + (size_t)row * (3 * DIM) + ch * 8);
    }
    cp_commit();
    asm volatile("cp.async.wait_group 0;" ::: "memory");
    __syncthreads();

    const uint32_t a_off =
        (uint32_t)(wr + (lane & 7) + ((lane >> 3) & 1) * 8) * ARS +
        (uint32_t)((lane >> 4) & 1) * 16;
    uint32_t qa[4][4];
#pragma unroll
    for (int kk = 0; kk < 4; ++kk) ldsm4(qa[kk], sbase + AQ + a_off + kk * 32);

    float m0 = -1e30f, m1 = -1e30f, l0 = 0.f, l1 = 0.f;
    float o[8][4];
#pragma unroll
    for (int ni = 0; ni < 8; ++ni)
#pragma unroll
        for (int r = 0; r < 4; ++r) o[ni][r] = 0.f;

    const __half* kbase = qkv + ((size_t)(b * SEQ)) * (3 * DIM) + DIM + h * DH;
    const __half* vbase = kbase + DIM;

    // K B-frag (non-trans): rows = seq(n), cols = dim(k)
    const uint32_t kb_off =
        (uint32_t)((lane & 7) + ((lane >> 4) & 1) * 8) * ARS +
        (uint32_t)((lane >> 3) & 1) * 16;
    // V B-frag (trans): rows = seq(k), cols = dim(n)
    const uint32_t vb_off =
        (uint32_t)((lane & 7) + ((lane >> 3) & 1) * 8) * ARS +
        (uint32_t)((lane >> 4) & 1) * 16;

    for (int jt = 0; jt < SEQ / 64; ++jt) {
        __syncthreads();   // previous tile fully consumed
#pragma unroll
        for (int i = 0; i < 4; ++i) {
            int c = tid + i * 128;
            int row = c >> 3, ch = c & 7;
            size_t goff = (size_t)(jt * 64 + row) * (3 * DIM) + ch * 8;
            cp_async16(sbase + AK + row * ARS + ch * 16, kbase + goff);
            cp_async16(sbase + AV + row * ARS + ch * 16, vbase + goff);
        }
        cp_commit();
        asm volatile("cp.async.wait_group 0;" ::: "memory");
        __syncthreads();

        // ---- S = Q K^T (scaled) ----
        float s[8][4];
#pragma unroll
        for (int ni = 0; ni < 8; ++ni)
#pragma unroll
            for (int r = 0; r < 4; ++r) s[ni][r] = 0.f;
#pragma unroll
        for (int kk = 0; kk < 4; ++kk) {
            uint32_t bf[4][4];
#pragma unroll
            for (int p = 0; p < 4; ++p)
                ldsm4(bf[p], sbase + AK + kb_off + p * 16 * ARS + kk * 32);
#pragma unroll
            for (int ni = 0; ni < 8; ++ni)
                mma_fp16(s[ni], qa[kk],
                         bf[ni >> 1][(ni & 1) * 2], bf[ni >> 1][(ni & 1) * 2 + 1]);
        }
#pragma unroll
        for (int ni = 0; ni < 8; ++ni)
#pragma unroll
            for (int r = 0; r < 4; ++r) s[ni][r] *= 0.125f;

        // ---- online softmax ----
        float rmax0 = -1e30f, rmax1 = -1e30f;
#pragma unroll
        for (int ni = 0; ni < 8; ++ni) {
            rmax0 = fmaxf(rmax0, fmaxf(s[ni][0], s[ni][1]));
            rmax1 = fmaxf(rmax1, fmaxf(s[ni][2], s[ni][3]));
        }
#pragma unroll
        for (int ofs = 1; ofs <= 2; ofs <<= 1) {
            rmax0 = fmaxf(rmax0, __shfl_xor_sync(0xffffffffu, rmax0, ofs));
            rmax1 = fmaxf(rmax1, __shfl_xor_sync(0xffffffffu, rmax1, ofs));
        }
        float mn0 = fmaxf(m0, rmax0), mn1 = fmaxf(m1, rmax1);
        float corr0 = __expf(m0 - mn0), corr1 = __expf(m1 - mn1);
        m0 = mn0; m1 = mn1;
        float ps0 = 0.f, ps1 = 0.f;
#pragma unroll
        for (int ni = 0; ni < 8; ++ni) {
            s[ni][0] = __expf(s[ni][0] - m0);
            s[ni][1] = __expf(s[ni][1] - m0);
            s[ni][2] = __expf(s[ni][2] - m1);
            s[ni][3] = __expf(s[ni][3] - m1);
            ps0 += s[ni][0] + s[ni][1];
            ps1 += s[ni][2] + s[ni][3];
        }
#pragma unroll
        for (int ofs = 1; ofs <= 2; ofs <<= 1) {
            ps0 += __shfl_xor_sync(0xffffffffu, ps0, ofs);
            ps1 += __shfl_xor_sync(0xffffffffu, ps1, ofs);
        }
        l0 = l0 * corr0 + ps0;
        l1 = l1 * corr1 + ps1;
#pragma unroll
        for (int ni = 0; ni < 8; ++ni) {
            o[ni][0] *= corr0; o[ni][1] *= corr0;
            o[ni][2] *= corr1; o[ni][3] *= corr1;
        }

        // ---- O += P V : P fragments come straight from s (no smem) ----
#pragma unroll
        for (int kk = 0; kk < 4; ++kk) {
            uint32_t pa[4];
            pa[0] = packh2(s[2 * kk][0],     s[2 * kk][1]);
            pa[1] = packh2(s[2 * kk][2],     s[2 * kk][3]);
            pa[2] = packh2(s[2 * kk + 1][0], s[2 * kk + 1][1]);
            pa[3] = packh2(s[2 * kk + 1][2], s[2 * kk + 1][3]);
            uint32_t vf[4][4];
#pragma unroll
            for (int p = 0; p < 4; ++p)
                ldsm4t(vf[p], sbase + AV + vb_off + kk * 16 * ARS + p * 32);
#pragma unroll
            for (int ni = 0; ni < 8; ++ni)
                mma_fp16(o[ni], pa,
                         vf[ni >> 1][(ni & 1) * 2], vf[ni >> 1][(ni & 1) * 2 + 1]);
        }
    }

    // ---- epilogue (fp16 out) ----
    float inv0 = 1.0f / l0, inv1 = 1.0f / l1;
    const int row0 = q0 + wr + g;
    const int row1 = row0 + 8;
    __half* ob0 = out + (size_t)(b * SEQ + row0) * DIM + h * DH;
    __half* ob1 = out + (size_t)(b * SEQ + row1) * DIM + h * DH;
#pragma unroll
    for (int ni = 0; ni < 8; ++ni) {
        int c = ni * 8 + 2 * t;
        *(__half2*)&ob0[c] = __float22half2_rn(make_float2(o[ni][0] * inv0, o[ni][1] * inv0));
        *(__half2*)&ob1[c] = __float22half2_rn(make_float2(o[ni][2] * inv1, o[ni][3] * inv1));
    }
}

// ---------------- host side ---------------------------------------------------
extern "C" void kernel_launch(void* const* d_in, const int* in_sizes, int n_in,
                              void* d_out, int out_size) {
    const float* x      = (const float*)d_in[0];
    const float* ln1_w  = (const float*)d_in[1];
    const float* ln1_b  = (const float*)d_in[2];
    const float* w_qkv  = (const float*)d_in[3];
    const float* w_o    = (const float*)d_in[4];
    const float* b_o    = (const float*)d_in[5];
    const float* ln2_w  = (const float*)d_in[6];
    const float* ln2_b  = (const float*)d_in[7];
    const float* w1     = (const float*)d_in[8];
    const float* b1     = (const float*)d_in[9];
    const float* w2     = (const float*)d_in[10];
    const float* b2     = (const float*)d_in[11];

    float* X = (float*)d_out;

    __half *pH, *pQKV, *pATT, *pMLP;
    __half *pWQKV, *pWO, *pW1, *pW2;
    cudaGetSymbolAddress((void**)&pH,    g_h);
    cudaGetSymbolAddress((void**)&pQKV,  g_qkv);
    cudaGetSymbolAddress((void**)&pATT,  g_attn);
    cudaGetSymbolAddress((void**)&pMLP,  g_mlp);
    cudaGetSymbolAddress((void**)&pWQKV, g_wqkv_t);
    cudaGetSymbolAddress((void**)&pWO,   g_wo_t);
    cudaGetSymbolAddress((void**)&pW1,   g_w1_t);
    cudaGetSymbolAddress((void**)&pW2,   g_w2_t);

    cudaFuncSetAttribute(fp16_gemm_kernel<false, false, false, true>,
                         cudaFuncAttributeMaxDynamicSharedMemorySize, GEMM_SMEM_BYTES);
    cudaFuncSetAttribute(fp16_gemm_kernel<true, true, false, false>,
                         cudaFuncAttributeMaxDynamicSharedMemorySize, GEMM_SMEM_BYTES);
    cudaFuncSetAttribute(fp16_gemm_kernel<true, false, true, true>,
                         cudaFuncAttributeMaxDynamicSharedMemorySize, GEMM_SMEM_BYTES);
    cudaFuncSetAttribute(attention_kernel,
                         cudaFuncAttributeMaxDynamicSharedMemorySize, ATT_SMEM_BYTES);

    // convert + transpose all weights to fp16 [N][K] once
    cvtT_kernel<<<dim3(3 * DIM / 32, DIM / 32, 6), dim3(32, 8)>>>(w_qkv, pWQKV, DIM, 3 * DIM);
    cvtT_kernel<<<dim3(DIM / 32, DIM / 32, 6), dim3(32, 8)>>>(w_o, pWO, DIM, DIM);
    cvtT_kernel<<<dim3(MLPD / 32, DIM / 32, 6), dim3(32, 8)>>>(w1, pW1, DIM, MLPD);
    cvtT_kernel<<<dim3(DIM / 32, MLPD / 32, 6), dim3(32, 8)>>>(w2, pW2, MLPD, DIM);

    cudaMemcpyAsync(X, x, (size_t)TOK * DIM * sizeof(float),
                    cudaMemcpyDeviceToDevice);

    for (int l = 0; l < 6; ++l) {
        const float* l1w = ln1_w + l * DIM;
        const float* l1b = ln1_b + l * DIM;
        const float* bo  = b_o + l * DIM;
        const float* l2w = ln2_w + l * DIM;
        const float* l2b = ln2_b + l * DIM;
        const float* B1  = b1 + l * MLPD;
        const float* B2  = b2 + l * DIM;
        const __half* wqkv = pWQKV + (size_t)l * DIM * 3 * DIM;
        const __half* wo   = pWO   + (size_t)l * DIM * DIM;
        const __half* W1   = pW1   + (size_t)l * DIM * MLPD;
        const __half* W2   = pW2   + (size_t)l * MLPD * DIM;

        // LN1 -> fp16
        layernorm_kernel<<<TOK, 256>>>(X, l1w, l1b, pH);
        // QKV: [4096,768] @ [768,2304] -> fp16
        fp16_gemm_kernel<false, false, false, true>
            <<<dim3(3 * DIM / 128, TOK / 128), 256, GEMM_SMEM_BYTES>>>(
                pH, wqkv, nullptr, pQKV, TOK, 3 * DIM, DIM);
        // fused fp16 tensor-core attention -> fp16
        attention_kernel<<<dim3(SEQ / 64, NB * HEADS), 128, ATT_SMEM_BYTES>>>(pQKV, pATT);
        // O-proj + bias + residual into X (fp32)
        fp16_gemm_kernel<true, true, false, false>
            <<<dim3(DIM / 128, TOK / 128), 256, GEMM_SMEM_BYTES>>>(
                pATT, wo, bo, X, TOK, DIM, DIM);
        // LN2 -> fp16
        layernorm_kernel<<<TOK, 256>>>(X, l2w, l2b, pH);
        // MLP1 + bias + exact GELU -> fp16
        fp16_gemm_kernel<true, false, true, true>
            <<<dim3(MLPD / 128, TOK / 128), 256, GEMM_SMEM_BYTES>>>(
                pH, W1, B1, pMLP, TOK, MLPD, DIM);
        // MLP2 + bias + residual into X (fp32)
        fp16_gemm_kernel<true, true, false, false>
            <<<dim3(DIM / 128, TOK / 128), 256, GEMM_SMEM_BYTES>>>(
                pMLP, W2, B2, X, TOK, DIM, MLPD);
    }
}

// round 12
// speedup vs baseline: 4.1937x; 1.0163x over previous
#include <cuda_runtime.h>
#include <cuda_fp16.h>
#include <math.h>
#include <stdint.h>

#define DIM 768
#define MLPD 3072
#define HEADS 12
#define DH 64
#define TOK 4096          // 4 * 1024
#define SEQ 1024
#define NB 4

// ---------------- scratch buffers (device globals; no allocation allowed) ----
__device__ __half   g_h[TOK * DIM];        // LN output (fp16)
__device__ __half   g_qkv[TOK * 3 * DIM];  // qkv projections (fp16)
__device__ __half   g_attn[TOK * DIM];     // attention output (fp16)
__device__ __half   g_mlp[TOK * MLPD];     // MLP hidden (fp16)

// fp16 weight copies, TRANSPOSED to [N][K] (converted once per launch)
__device__ __half g_wqkv_t[6 * DIM * 3 * DIM];
__device__ __half g_wo_t[6 * DIM * DIM];
__device__ __half g_w1_t[6 * DIM * MLPD];
__device__ __half g_w2_t[6 * MLPD * DIM];

// single dynamic shared memory symbol, cast per kernel
extern __shared__ char dyn_smem[];

// ---------------- helpers ------------------------------------------------------
__device__ __forceinline__ void mma_fp16(float c[4], const uint32_t a[4],
                                         uint32_t b0, uint32_t b1) {
    asm volatile(
        "mma.sync.aligned.m16n8k16.row.col.f32.f16.f16.f32 "
        "{%0,%1,%2,%3}, {%4,%5,%6,%7}, {%8,%9}, {%0,%1,%2,%3};"
        : "+f"(c[0]), "+f"(c[1]), "+f"(c[2]), "+f"(c[3])
        : "r"(a[0]), "r"(a[1]), "r"(a[2]), "r"(a[3]), "r"(b0), "r"(b1));
}

__device__ __forceinline__ void ldsm4(uint32_t r[4], uint32_t saddr) {
    asm volatile("ldmatrix.sync.aligned.m8n8.x4.shared.b16 {%0,%1,%2,%3}, [%4];"
                 : "=r"(r[0]), "=r"(r[1]), "=r"(r[2]), "=r"(r[3])
                 : "r"(saddr));
}

__device__ __forceinline__ void ldsm4t(uint32_t r[4], uint32_t saddr) {
    asm volatile("ldmatrix.sync.aligned.m8n8.x4.trans.shared.b16 {%0,%1,%2,%3}, [%4];"
                 : "=r"(r[0]), "=r"(r[1]), "=r"(r[2]), "=r"(r[3])
                 : "r"(saddr));
}

__device__ __forceinline__ void cp_async16(uint32_t saddr, const void* gptr) {
    asm volatile("cp.async.cg.shared.global [%0], [%1], 16;"
                 :: "r"(saddr), "l"(gptr));
}
__device__ __forceinline__ void cp_commit() {
    asm volatile("cp.async.commit_group;");
}

__device__ __forceinline__ uint32_t packh2(float a, float b) {
    __half2 h = __float22half2_rn(make_float2(a, b));
    return *(uint32_t*)&h;
}

// ---------------- fp32 [K,N] -> fp16 [N,K] transpose-convert -----------------
// block (32,8); grid (N/32, K/32, layers)
__global__ void cvtT_kernel(const float* __restrict__ in,
                            __half* __restrict__ out, int K, int N) {
    __shared__ __half tile[32][34];
    const size_t lofs = (size_t)blockIdx.z * K * N;
    const float* inL = in + lofs;
    __half* outL = out + lofs;
    int k0 = blockIdx.y * 32, n0 = blockIdx.x * 32;
#pragma unroll
    for (int i = threadIdx.y; i < 32; i += 8)
        tile[i][threadIdx.x] =
            __float2half_rn(inL[(size_t)(k0 + i) * N + n0 + threadIdx.x]);
    __syncthreads();
#pragma unroll
    for (int i = threadIdx.y; i < 32; i += 8)
        outL[(size_t)(n0 + i) * K + k0 + threadIdx.x] = tile[threadIdx.x][i];
}

// ---------------- LayerNorm: one WARP per row, 4 rows/block, writes fp16 -----
__global__ __launch_bounds__(128) void layernorm_kernel(
    const float* __restrict__ x, const float* __restrict__ w,
    const float* __restrict__ b, __half* __restrict__ out) {
    const int lane = threadIdx.x & 31;
    const int wrp  = threadIdx.x >> 5;
    const int row  = blockIdx.x * 4 + wrp;

    const float4* xr = (const float4*)(x + (size_t)row * DIM);
    float4 v[6];
    float s = 0.f, ss = 0.f;
#pragma unroll
    for (int i = 0; i < 6; ++i) {
        float4 t = xr[lane + 32 * i];
        v[i] = t;
        s  += t.x + t.y + t.z + t.w;
        ss += t.x * t.x + t.y * t.y + t.z * t.z + t.w * t.w;
    }
#pragma unroll
    for (int o = 16; o; o >>= 1) {
        s  += __shfl_xor_sync(0xffffffffu, s, o);
        ss += __shfl_xor_sync(0xffffffffu, ss, o);
    }
    float mean = s * (1.0f / DIM);
    float rstd = rsqrtf(ss * (1.0f / DIM) - mean * mean + 1e-5f);

    const float4* w4 = (const float4*)w;
    const float4* b4 = (const float4*)b;
    uint2* orow = (uint2*)(out + (size_t)row * DIM);
#pragma unroll
    for (int i = 0; i < 6; ++i) {
        int idx = lane + 32 * i;
        float4 wv = w4[idx], bv = b4[idx];
        float4 t = v[i];
        uint2 o2;
        o2.x = packh2((t.x - mean) * rstd * wv.x + bv.x,
                      (t.y - mean) * rstd * wv.y + bv.y);
        o2.y = packh2((t.z - mean) * rstd * wv.z + bv.z,
                      (t.w - mean) * rstd * wv.w + bv.w);
        orow[idx] = o2;
    }
}

// ---------------- FP16 tensor-core GEMM, 3-stage cp.async + ldmatrix ----------
// C[M,N] = op( A[M,K] @ B^T + bias ) (+ residual), A [M][K] fp16, B [N][K] fp16.
// block tile 128x128, K-tile 64, 8 warps (4x2), warp tile 32x64.
#define GSTAGES 3
#define RSB 144                     // smem row stride bytes (36 words)
#define A_STG (128 * RSB)           // 18432 B
#define B_STG (128 * RSB)
#define SM_A 0
#define SM_B (GSTAGES * A_STG)
#define GEMM_SMEM_BYTES (GSTAGES * (A_STG + B_STG))   // 110592

template <bool HAS_BIAS, bool RESID, bool DO_GELU, bool OUT_HALF>
__global__ __launch_bounds__(256, 2) void fp16_gemm_kernel(
    const __half* __restrict__ A, const __half* __restrict__ B,
    const float* __restrict__ bias, void* __restrict__ Cv,
    int M, int N, int K) {
    const uint32_t sbase = (uint32_t)__cvta_generic_to_shared(dyn_smem);

    const int tid   = threadIdx.x;
    const int lane  = tid & 31;
    const int wid   = tid >> 5;
    const int group = lane >> 2;   // 0..7
    const int tig   = lane & 3;    // 0..3
    const int wm0   = (wid >> 1) * 32;
    const int wn0   = (wid & 1) * 64;

    const __half* Ab = A + (size_t)(blockIdx.y * 128) * K;
    const __half* Bb = B + (size_t)(blockIdx.x * 128) * K;  // [N][K]

    const uint32_t a_off =
        (uint32_t)(wm0 + (lane & 7) + (((lane >> 3) & 1) * 8)) * RSB +
        (uint32_t)((lane >> 4) & 1) * 16;
    const uint32_t b_off =
        (uint32_t)(wn0 + (lane & 7) + (((lane >> 4) & 1) * 8)) * RSB +
        (uint32_t)((lane >> 3) & 1) * 16;

    const int T = K / 64;

#define ISSUE_TILE(kt, s)                                                     \
    do {                                                                      \
        uint32_t abase_ = sbase + SM_A + (s) * A_STG;                         \
        uint32_t bbase_ = sbase + SM_B + (s) * B_STG;                         \
        _Pragma("unroll")                                                     \
        for (int i_ = 0; i_ < 4; ++i_) {                                      \
            int c_ = tid + i_ * 256;                                          \
            int row_ = c_ >> 3, col_ = c_ & 7;                                \
            cp_async16(abase_ + row_ * RSB + col_ * 16,                       \
                       Ab + (size_t)row_ * K + (kt) + col_ * 8);              \
            cp_async16(bbase_ + row_ * RSB + col_ * 16,                       \
                       Bb + (size_t)row_ * K + (kt) + col_ * 8);              \
        }                                                                     \
        cp_commit();                                                          \
    } while (0)

    ISSUE_TILE(0, 0);
    ISSUE_TILE(64, 1);

    float acc[2][8][4];
#pragma unroll
    for (int mi = 0; mi < 2; ++mi)
#pragma unroll
        for (int ni = 0; ni < 8; ++ni)
#pragma unroll
            for (int r = 0; r < 4; ++r) acc[mi][ni][r] = 0.f;

    for (int it = 0; it < T; ++it) {
        asm volatile("cp.async.wait_group 1;" ::: "memory");
        __syncthreads();
        if (it + 2 < T) ISSUE_TILE((it + 2) * 64, (it + 2) % GSTAGES);

        const int sb = it % GSTAGES;
        const uint32_t aBase = sbase + SM_A + sb * A_STG + a_off;
        const uint32_t bBase = sbase + SM_B + sb * B_STG + b_off;

#pragma unroll
        for (int kk = 0; kk < 4; ++kk) {
            uint32_t af[2][4];
            ldsm4(af[0], aBase + kk * 32);
            ldsm4(af[1], aBase + 16 * RSB + kk * 32);
            uint32_t bf[4][4];
#pragma unroll
            for (int p = 0; p < 4; ++p)
                ldsm4(bf[p], bBase + p * 16 * RSB + kk * 32);
#pragma unroll
            for (int ni = 0; ni < 8; ++ni) {
                uint32_t b0 = bf[ni >> 1][(ni & 1) * 2 + 0];
                uint32_t b1 = bf[ni >> 1][(ni & 1) * 2 + 1];
                mma_fp16(acc[0][ni], af[0], b0, b1);
                mma_fp16(acc[1][ni], af[1], b0, b1);
            }
        }
    }
#undef ISSUE_TILE

    // epilogue
    const int base_m = blockIdx.y * 128 + wm0;
    const int base_n = blockIdx.x * 128 + wn0;
#pragma unroll
    for (int mi = 0; mi < 2; ++mi) {
#pragma unroll
        for (int rr = 0; rr < 2; ++rr) {
            int row = base_m + mi * 16 + rr * 8 + group;
#pragma unroll
            for (int ni = 0; ni < 8; ++ni) {
                int col = base_n + ni * 8 + tig * 2;
                float v0 = acc[mi][ni][rr * 2 + 0];
                float v1 = acc[mi][ni][rr * 2 + 1];
                if (HAS_BIAS) { v0 += bias[col]; v1 += bias[col + 1]; }
                if (DO_GELU) {
                    v0 = 0.5f * v0 * (1.0f + erff(v0 * 0.70710678118654752f));
                    v1 = 0.5f * v1 * (1.0f + erff(v1 * 0.70710678118654752f));
                }
                if (OUT_HALF) {
                    __half2* p = (__half2*)((__half*)Cv + (size_t)row * N + col);
                    *p = __float22half2_rn(make_float2(v0, v1));
                } else {
                    float* p = (float*)Cv + (size_t)row * N + col;
                    if (RESID) {
                        float2 r = *(float2*)p;
                        v0 += r.x; v1 += r.y;
                    }
                    *(float2*)p = make_float2(v0, v1);
                }
            }
        }
    }
}

// ---------------- FP16 flash attention: Q-tile 128, 2-stage K/V pipeline ------
// grid: (SEQ/128, NB*HEADS), block 256 (8 warps), each warp owns 16 Q rows.
#define ARS 144                        // row stride bytes (64 halves + 8 pad)
#define AQ 0                           // 128 rows  -> 18432 B
#define AK (128 * ARS)                 // 2 stages x 64 rows
#define KSTG (64 * ARS)                // 9216 B
#define AV (AK + 2 * KSTG)
#define ATT_SMEM_BYTES (AV + 2 * KSTG) // 55296 B

__global__ __launch_bounds__(256) void attention_kernel(
    const __half* __restrict__ qkv, __half* __restrict__ out) {
    const uint32_t sbase = (uint32_t)__cvta_generic_to_shared(dyn_smem);
    const int tid  = threadIdx.x;
    const int lane = tid & 31;
    const int w    = tid >> 5;          // 0..7
    const int g    = lane >> 2;
    const int t    = lane & 3;
    const int wr   = w * 16;            // 0..112

    const int bh = blockIdx.y;
    const int b  = bh / HEADS;
    const int h  = bh % HEADS;
    const int q0 = blockIdx.x * 128;

    const __half* qbase = qkv + ((size_t)(b * SEQ + q0)) * (3 * DIM) + h * DH;
    const __half* kbase = qkv + ((size_t)(b * SEQ)) * (3 * DIM) + DIM + h * DH;
    const __half* vbase = kbase + DIM;

#define ISSUE_KV(jt, s)                                                       \
    do {                                                                      \
        _Pragma("unroll")                                                     \
        for (int i_ = 0; i_ < 2; ++i_) {                                      \
            int c_ = tid + i_ * 256;                                          \
            int row_ = c_ >> 3, ch_ = c_ & 7;                                 \
            size_t goff_ = (size_t)((jt) * 64 + row_) * (3 * DIM) + ch_ * 8;  \
            cp_async16(sbase + AK + (s) * KSTG + row_ * ARS + ch_ * 16,       \
                       kbase + goff_);                                        \
            cp_async16(sbase + AV + (s) * KSTG + row_ * ARS + ch_ * 16,       \
                       vbase + goff_);                                        \
        }                                                                     \
        cp_commit();                                                          \
    } while (0)

    // ---- stage Q tile (group 0) and K/V tile 0 (group 1) --------------------
#pragma unroll
    for (int i = 0; i < 4; ++i) {
        int c = tid + i * 256;
        int row = c >> 3, ch = c & 7;
        cp_async16(sbase + AQ + row * ARS + ch * 16,
                   qbase + (size_t)row * (3 * DIM) + ch * 8);
    }
    cp_commit();
    ISSUE_KV(0, 0);
    asm volatile("cp.async.wait_group 1;" ::: "memory");  // Q done
    __syncthreads();

    const uint32_t a_off =
        (uint32_t)(wr + (lane & 7) + ((lane >> 3) & 1) * 8) * ARS +
        (uint32_t)((lane >> 4) & 1) * 16;
    uint32_t qa[4][4];
#pragma unroll
    for (int kk = 0; kk < 4; ++kk) ldsm4(qa[kk], sbase + AQ + a_off + kk * 32);

    float m0 = -1e30f, m1 = -1e30f, l0 = 0.f, l1 = 0.f;
    float o[8][4];
#pragma unroll
    for (int ni = 0; ni < 8; ++ni)
#pragma unroll
        for (int r = 0; r < 4; ++r) o[ni][r] = 0.f;

    const uint32_t kb_off =
        (uint32_t)((lane & 7) + ((lane >> 4) & 1) * 8) * ARS +
        (uint32_t)((lane >> 3) & 1) * 16;
    const uint32_t vb_off =
        (uint32_t)((lane & 7) + ((lane >> 3) & 1) * 8) * ARS +
        (uint32_t)((lane >> 4) & 1) * 16;

    for (int jt = 0; jt < SEQ / 64; ++jt) {
        if (jt > 0) __syncthreads();     // all warps done with stage (jt+1)&1
        if (jt + 1 < SEQ / 64) {
            ISSUE_KV(jt + 1, (jt + 1) & 1);
            asm volatile("cp.async.wait_group 1;" ::: "memory");
        } else {
            asm volatile("cp.async.wait_group 0;" ::: "memory");
        }
        __syncthreads();                 // tile jt visible to all warps

        const uint32_t kBase = sbase + AK + (jt & 1) * KSTG + kb_off;
        const uint32_t vBase = sbase + AV + (jt & 1) * KSTG + vb_off;

        // ---- S = Q K^T (scaled) ----
        float s[8][4];
#pragma unroll
        for (int ni = 0; ni < 8; ++ni)
#pragma unroll
            for (int r = 0; r < 4; ++r) s[ni][r] = 0.f;
#pragma unroll
        for (int kk = 0; kk < 4; ++kk) {
            uint32_t bf[4][4];
#pragma unroll
            for (int p = 0; p < 4; ++p)
                ldsm4(bf[p], kBase + p * 16 * ARS + kk * 32);
#pragma unroll
            for (int ni = 0; ni < 8; ++ni)
                mma_fp16(s[ni], qa[kk],
                         bf[ni >> 1][(ni & 1) * 2], bf[ni >> 1][(ni & 1) * 2 + 1]);
        }
#pragma unroll
        for (int ni = 0; ni < 8; ++ni)
#pragma unroll
            for (int r = 0; r < 4; ++r) s[ni][r] *= 0.125f;

        // ---- online softmax ----
        float rmax0 = -1e30f, rmax1 = -1e30f;
#pragma unroll
        for (int ni = 0; ni < 8; ++ni) {
            rmax0 = fmaxf(rmax0, fmaxf(s[ni][0], s[ni][1]));
            rmax1 = fmaxf(rmax1, fmaxf(s[ni][2], s[ni][3]));
        }
#pragma unroll
        for (int ofs = 1; ofs <= 2; ofs <<= 1) {
            rmax0 = fmaxf(rmax0, __shfl_xor_sync(0xffffffffu, rmax0, ofs));
            rmax1 = fmaxf(rmax1, __shfl_xor_sync(0xffffffffu, rmax1, ofs));
        }
        float mn0 = fmaxf(m0, rmax0), mn1 = fmaxf(m1, rmax1);
        float corr0 = __expf(m0 - mn0), corr1 = __expf(m1 - mn1);
        m0 = mn0; m1 = mn1;
        float ps0 = 0.f, ps1 = 0.f;
#pragma unroll
        for (int ni = 0; ni < 8; ++ni) {
            s[ni][0] = __expf(s[ni][0] - m0);
            s[ni][1] = __expf(s[ni][1] - m0);
            s[ni][2] = __expf(s[ni][2] - m1);
            s[ni][3] = __expf(s[ni][3] - m1);
            ps0 += s[ni][0] + s[ni][1];
            ps1 += s[ni][2] + s[ni][3];
        }
#pragma unroll
        for (int ofs = 1; ofs <= 2; ofs <<= 1) {
            ps0 += __shfl_xor_sync(0xffffffffu, ps0, ofs);
            ps1 += __shfl_xor_sync(0xffffffffu, ps1, ofs);
        }
        l0 = l0 * corr0 + ps0;
        l1 = l1 * corr1 + ps1;
#pragma unroll
        for (int ni = 0; ni < 8; ++ni) {
            o[ni][0] *= corr0; o[ni][1] *= corr0;
            o[ni][2] *= corr1; o[ni][3] *= corr1;
        }

        // ---- O += P V : P fragments straight from s ----
#pragma unroll
        for (int kk = 0; kk < 4; ++kk) {
            uint32_t pa[4];
            pa[0] = packh2(s[2 * kk][0],     s[2 * kk][1]);
            pa[1] = packh2(s[2 * kk][2],     s[2 * kk][3]);
            pa[2] = packh2(s[2 * kk + 1][0], s[2 * kk + 1][1]);
            pa[3] = packh2(s[2 * kk + 1][2], s[2 * kk + 1][3]);
            uint32_t vf[4][4];
#pragma unroll
            for (int p = 0; p < 4; ++p)
                ldsm4t(vf[p], vBase + kk * 16 * ARS + p * 32);
#pragma unroll
            for (int ni = 0; ni < 8; ++ni)
                mma_fp16(o[ni], pa,
                         vf[ni >> 1][(ni & 1) * 2], vf[ni >> 1][(ni & 1) * 2 + 1]);
        }
    }
#undef ISSUE_KV

    // ---- epilogue (fp16 out) ----
    float inv0 = 1.0f / l0, inv1 = 1.0f / l1;
    const int row0 = q0 + wr + g;
    const int row1 = row0 + 8;
    __half* ob0 = out + (size_t)(b * SEQ + row0) * DIM + h * DH;
    __half* ob1 = out + (size_t)(b * SEQ + row1) * DIM + h * DH;
#pragma unroll
    for (int ni = 0; ni < 8; ++ni) {
        int c = ni * 8 + 2 * t;
        *(__half2*)&ob0[c] = __float22half2_rn(make_float2(o[ni][0] * inv0, o[ni][1] * inv0));
        *(__half2*)&ob1[c] = __float22half2_rn(make_float2(o[ni][2] * inv1, o[ni][3] * inv1));
    }
}

// ---------------- host side ---------------------------------------------------
extern "C" void kernel_launch(void* const* d_in, const int* in_sizes, int n_in,
                              void* d_out, int out_size) {
    const float* x      = (const float*)d_in[0];
    const float* ln1_w  = (const float*)d_in[1];
    const float* ln1_b  = (const float*)d_in[2];
    const float* w_qkv  = (const float*)d_in[3];
    const float* w_o    = (const float*)d_in[4];
    const float* b_o    = (const float*)d_in[5];
    const float* ln2_w  = (const float*)d_in[6];
    const float* ln2_b  = (const float*)d_in[7];
    const float* w1     = (const float*)d_in[8];
    const float* b1     = (const float*)d_in[9];
    const float* w2     = (const float*)d_in[10];
    const float* b2     = (const float*)d_in[11];

    float* X = (float*)d_out;

    __half *pH, *pQKV, *pATT, *pMLP;
    __half *pWQKV, *pWO, *pW1, *pW2;
    cudaGetSymbolAddress((void**)&pH,    g_h);
    cudaGetSymbolAddress((void**)&pQKV,  g_qkv);
    cudaGetSymbolAddress((void**)&pATT,  g_attn);
    cudaGetSymbolAddress((void**)&pMLP,  g_mlp);
    cudaGetSymbolAddress((void**)&pWQKV, g_wqkv_t);
    cudaGetSymbolAddress((void**)&pWO,   g_wo_t);
    cudaGetSymbolAddress((void**)&pW1,   g_w1_t);
    cudaGetSymbolAddress((void**)&pW2,   g_w2_t);

    cudaFuncSetAttribute(fp16_gemm_kernel<false, false, false, true>,
                         cudaFuncAttributeMaxDynamicSharedMemorySize, GEMM_SMEM_BYTES);
    cudaFuncSetAttribute(fp16_gemm_kernel<true, true, false, false>,
                         cudaFuncAttributeMaxDynamicSharedMemorySize, GEMM_SMEM_BYTES);
    cudaFuncSetAttribute(fp16_gemm_kernel<true, false, true, true>,
                         cudaFuncAttributeMaxDynamicSharedMemorySize, GEMM_SMEM_BYTES);
    cudaFuncSetAttribute(attention_kernel,
                         cudaFuncAttributeMaxDynamicSharedMemorySize, ATT_SMEM_BYTES);

    // convert + transpose all weights to fp16 [N][K] once
    cvtT_kernel<<<dim3(3 * DIM / 32, DIM / 32, 6), dim3(32, 8)>>>(w_qkv, pWQKV, DIM, 3 * DIM);
    cvtT_kernel<<<dim3(DIM / 32, DIM / 32, 6), dim3(32, 8)>>>(w_o, pWO, DIM, DIM);
    cvtT_kernel<<<dim3(MLPD / 32, DIM / 32, 6), dim3(32, 8)>>>(w1, pW1, DIM, MLPD);
    cvtT_kernel<<<dim3(DIM / 32, MLPD / 32, 6), dim3(32, 8)>>>(w2, pW2, MLPD, DIM);

    cudaMemcpyAsync(X, x, (size_t)TOK * DIM * sizeof(float),
                    cudaMemcpyDeviceToDevice);

    for (int l = 0; l < 6; ++l) {
        const float* l1w = ln1_w + l * DIM;
        const float* l1b = ln1_b + l * DIM;
        const float* bo  = b_o + l * DIM;
        const float* l2w = ln2_w + l * DIM;
        const float* l2b = ln2_b + l * DIM;
        const float* B1  = b1 + l * MLPD;
        const float* B2  = b2 + l * DIM;
        const __half* wqkv = pWQKV + (size_t)l * DIM * 3 * DIM;
        const __half* wo   = pWO   + (size_t)l * DIM * DIM;
        const __half* W1   = pW1   + (size_t)l * DIM * MLPD;
        const __half* W2   = pW2   + (size_t)l * MLPD * DIM;

        // LN1 -> fp16
        layernorm_kernel<<<TOK / 4, 128>>>(X, l1w, l1b, pH);
        // QKV: [4096,768] @ [768,2304] -> fp16
        fp16_gemm_kernel<false, false, false, true>
            <<<dim3(3 * DIM / 128, TOK / 128), 256, GEMM_SMEM_BYTES>>>(
                pH, wqkv, nullptr, pQKV, TOK, 3 * DIM, DIM);
        // fused fp16 tensor-core attention -> fp16
        attention_kernel<<<dim3(SEQ / 128, NB * HEADS), 256, ATT_SMEM_BYTES>>>(pQKV, pATT);
        // O-proj + bias + residual into X (fp32)
        fp16_gemm_kernel<true, true, false, false>
            <<<dim3(DIM / 128, TOK / 128), 256, GEMM_SMEM_BYTES>>>(
                pATT, wo, bo, X, TOK, DIM, DIM);
        // LN2 -> fp16
        layernorm_kernel<<<TOK / 4, 128>>>(X, l2w, l2b, pH);
        // MLP1 + bias + exact GELU -> fp16
        fp16_gemm_kernel<true, false, true, true>
            <<<dim3(MLPD / 128, TOK / 128), 256, GEMM_SMEM_BYTES>>>(
                pH, W1, B1, pMLP, TOK, MLPD, DIM);
        // MLP2 + bias + residual into X (fp32)
        fp16_gemm_kernel<true, true, false, false>
            <<<dim3(DIM / 128, TOK / 128), 256, GEMM_SMEM_BYTES>>>(
                pMLP, W2, B2, X, TOK, DIM, MLPD);
    }
}